// round 12
// baseline (speedup 1.0000x reference)
// VGG16_FPN — R12: 256-thread/32x64-tile MMA kernels with hi/lo tf32 tiles in
// SMEM (split once per tile at copy time; inner loop is pure LDS+mma).
#include <cuda_runtime.h>
#include <math.h>
#include <stdint.h>

#define BATCH   8
#define CC      512
#define HW      48
#define NN      2304
#define BN      (BATCH * NN)
#define MAXDEG  12
#define SCALE   0.044194173824159216f
#define LN_EPS  1e-5f
#define NSPLIT  2
#define CPS     (NN / NSPLIT)

__device__ float g_ssq [BN];
__device__ int   g_sidx[NN * 3];
__device__ int   g_deg [BN];
__device__ int   g_src [BN * MAXDEG];
__device__ float g_pd  [BN * NSPLIT * 3];
__device__ int   g_pj  [BN * NSPLIT * 3];
__device__ float g_q   [(size_t)BN * CC];
__device__ float g_k   [(size_t)BN * CC];
__device__ float g_v   [(size_t)BN * CC];
__device__ float g_sk  [(size_t)BN * CC];
__device__ float g_h1  [(size_t)BN * CC];

__device__ __forceinline__ uint32_t f2tf32(float x) {
    uint32_t r;
    asm("cvt.rna.tf32.f32 %0, %1;" : "=r"(r) : "f"(x));
    return r;
}

__device__ __forceinline__ void cvt_store(float* __restrict__ Sh,
                                          float* __restrict__ Sl,
                                          int off, float v) {
    uint32_t hb = f2tf32(v);
    float hf = __uint_as_float(hb);
    Sh[off] = hf;
    Sl[off] = __uint_as_float(f2tf32(v - hf));
}

__device__ __forceinline__ void mma8(float* c, const uint32_t* a,
                                     uint32_t b0, uint32_t b1) {
    asm volatile(
        "mma.sync.aligned.m16n8k8.row.col.f32.tf32.tf32.f32 "
        "{%0,%1,%2,%3},{%4,%5,%6,%7},{%8,%9},{%0,%1,%2,%3};"
        : "+f"(c[0]), "+f"(c[1]), "+f"(c[2]), "+f"(c[3])
        : "r"(a[0]), "r"(a[1]), "r"(a[2]), "r"(a[3]), "r"(b0), "r"(b1));
}

__device__ __forceinline__ void mma3(float* c,
                                     const uint32_t* ah, const uint32_t* al,
                                     uint32_t bh0, uint32_t bh1,
                                     uint32_t bl0, uint32_t bl1) {
    mma8(c, ah, bh0, bh1);
    mma8(c, ah, bl0, bl1);
    mma8(c, al, bh0, bh1);
}

__device__ __forceinline__ void top3_insert(float d, int j,
                                            float& d0, int& j0,
                                            float& d1, int& j1,
                                            float& d2, int& j2) {
    bool b2 = (d < d2) || (d == d2 && j < j2);
    if (!b2) return;
    bool b1 = (d < d1) || (d == d1 && j < j1);
    if (b1) {
        d2 = d1; j2 = j1;
        bool b0 = (d < d0) || (d == d0 && j < j0);
        if (b0) { d1 = d0; j1 = j0; d0 = d; j0 = j; }
        else    { d1 = d;  j1 = j; }
    } else {
        d2 = d; j2 = j;
    }
}

__global__ void zero_deg_kernel() {
    int i = blockIdx.x * blockDim.x + threadIdx.x;
    if (i < BN) g_deg[i] = 0;
}

__global__ void ssq_kernel(const float* __restrict__ x) {
    int warp = (blockIdx.x * blockDim.x + threadIdx.x) >> 5;
    int lane = threadIdx.x & 31;
    if (warp >= BN) return;
    const float* row = x + (size_t)warp * CC;
    float s = 0.f;
    for (int c = lane; c < CC; c += 32) { float v = row[c]; s += v * v; }
    #pragma unroll
    for (int off = 16; off; off >>= 1) s += __shfl_xor_sync(0xffffffffu, s, off);
    if (lane == 0) g_ssq[warp] = s;
}

__global__ void spatial_topk_kernel() {
    int i = blockIdx.x * blockDim.x + threadIdx.x;
    if (i >= NN) return;
    int yi = i / HW, xi = i % HW;
    float d0 = INFINITY, d1 = INFINITY, d2 = INFINITY;
    int   j0 = 0x7fffffff, j1 = 0x7fffffff, j2 = 0x7fffffff;
    for (int j = 0; j < NN; j++) {
        int yj = j / HW, xj = j % HW;
        int dy = yi - yj, dx = xi - xj;
        float d = sqrtf((float)(dy * dy + dx * dx));
        top3_insert(d, j, d0, j0, d1, j1, d2, j2);
    }
    g_sidx[i * 3 + 0] = j0;
    g_sidx[i * 3 + 1] = j1;
    g_sidx[i * 3 + 2] = j2;
}

// ---------------------------------------------------------------------------
// Fused Gram + feature-topk. 256 threads, warp tile 32x64, hi/lo SMEM tiles
// (split at copy), register-prefetch double buffering.
// dynamic smem: 8 * 2560 floats = 81920 B
// ---------------------------------------------------------------------------
#define GA 2560   // 128 rows * 20 floats

__global__ void __launch_bounds__(256, 2) gram_topk_kernel(const float* __restrict__ X) {
    extern __shared__ float sm[];
    float* AhB[2] = { sm + 0 * GA, sm + 1 * GA };
    float* AlB[2] = { sm + 2 * GA, sm + 3 * GA };
    float* BhB[2] = { sm + 4 * GA, sm + 5 * GA };
    float* BlB[2] = { sm + 6 * GA, sm + 7 * GA };

    __shared__ float s_rd[128][3];
    __shared__ int   s_rj[128][3];
    __shared__ float s_cd[128][2][3];
    __shared__ int   s_cj[128][2][3];
    __shared__ float s_sq[128];
    __shared__ float s_si[128];

    int split = blockIdx.x;
    int row0  = blockIdx.y * 128;
    int b     = blockIdx.z;
    const float* Xb = X + (size_t)b * NN * CC;
    int bNN = b * NN;

    int tid = threadIdx.x;
    int warp = tid >> 5, lane = tid & 31;
    int wm = (warp >> 1) * 32;     // 4 row-groups of 32
    int wn = (warp & 1) * 64;      // 2 col-groups of 64
    int g = lane >> 2, t4 = lane & 3;
    int warpN = (warp & 1);

    if (tid < 128) {
        s_rd[tid][0] = INFINITY; s_rd[tid][1] = INFINITY; s_rd[tid][2] = INFINITY;
        s_rj[tid][0] = 0x7fffffff; s_rj[tid][1] = 0x7fffffff; s_rj[tid][2] = 0x7fffffff;
        s_si[tid] = g_ssq[bNN + row0 + tid];
    }

    int m_ld  = tid >> 2;              // 0..63 base row for copies
    int k4_ld = (tid & 3) << 2;

    for (int ct = 0; ct < CPS / 128; ct++) {
        int col0 = split * CPS + ct * 128;
        if (tid < 128) s_sq[tid] = g_ssq[bNN + col0 + tid];
        __syncthreads();   // protect s_sq/h-lo buffers from previous iter readers

        // prologue: load + split k-tile 0 into buffer 0
        #pragma unroll
        for (int i = 0; i < 2; i++) {
            int m = m_ld + 64 * i;
            int o = m * 20 + k4_ld;
            float4 va = *(const float4*)(Xb + (size_t)(row0 + m) * CC + k4_ld);
            cvt_store(AhB[0], AlB[0], o + 0, va.x); cvt_store(AhB[0], AlB[0], o + 1, va.y);
            cvt_store(AhB[0], AlB[0], o + 2, va.z); cvt_store(AhB[0], AlB[0], o + 3, va.w);
            float4 vb = *(const float4*)(Xb + (size_t)(col0 + m) * CC + k4_ld);
            cvt_store(BhB[0], BlB[0], o + 0, vb.x); cvt_store(BhB[0], BlB[0], o + 1, vb.y);
            cvt_store(BhB[0], BlB[0], o + 2, vb.z); cvt_store(BhB[0], BlB[0], o + 3, vb.w);
        }
        __syncthreads();

        float acc[2][8][4] = {};
        for (int k0 = 0; k0 < CC; k0 += 16) {
            int cur = (k0 >> 4) & 1;
            bool hasnext = (k0 + 16 < CC);
            float4 va[2], vb[2];
            if (hasnext) {
                #pragma unroll
                for (int i = 0; i < 2; i++) {
                    int m = m_ld + 64 * i;
                    va[i] = *(const float4*)(Xb + (size_t)(row0 + m) * CC + k0 + 16 + k4_ld);
                    vb[i] = *(const float4*)(Xb + (size_t)(col0 + m) * CC + k0 + 16 + k4_ld);
                }
            }
            const float* Ah = AhB[cur]; const float* Al = AlB[cur];
            const float* Bh = BhB[cur]; const float* Bl = BlB[cur];
            #pragma unroll
            for (int kk = 0; kk < 16; kk += 8) {
                uint32_t ah[2][4], al[2][4];
                #pragma unroll
                for (int mt = 0; mt < 2; mt++) {
                    int r0i = (wm + mt * 16 + g) * 20 + kk + t4;
                    int r1i = r0i + 8 * 20;
                    ah[mt][0] = __float_as_uint(Ah[r0i]);
                    ah[mt][1] = __float_as_uint(Ah[r1i]);
                    ah[mt][2] = __float_as_uint(Ah[r0i + 4]);
                    ah[mt][3] = __float_as_uint(Ah[r1i + 4]);
                    al[mt][0] = __float_as_uint(Al[r0i]);
                    al[mt][1] = __float_as_uint(Al[r1i]);
                    al[mt][2] = __float_as_uint(Al[r0i + 4]);
                    al[mt][3] = __float_as_uint(Al[r1i + 4]);
                }
                #pragma unroll
                for (int nt = 0; nt < 8; nt++) {
                    int nb = (wn + nt * 8 + g) * 20 + kk + t4;
                    uint32_t bh0 = __float_as_uint(Bh[nb]);
                    uint32_t bh1 = __float_as_uint(Bh[nb + 4]);
                    uint32_t bl0 = __float_as_uint(Bl[nb]);
                    uint32_t bl1 = __float_as_uint(Bl[nb + 4]);
                    #pragma unroll
                    for (int mt = 0; mt < 2; mt++)
                        mma3(acc[mt][nt], ah[mt], al[mt], bh0, bh1, bl0, bl1);
                }
            }
            if (hasnext) {
                int nxt = cur ^ 1;
                #pragma unroll
                for (int i = 0; i < 2; i++) {
                    int o = (m_ld + 64 * i) * 20 + k4_ld;
                    cvt_store(AhB[nxt], AlB[nxt], o + 0, va[i].x);
                    cvt_store(AhB[nxt], AlB[nxt], o + 1, va[i].y);
                    cvt_store(AhB[nxt], AlB[nxt], o + 2, va[i].z);
                    cvt_store(AhB[nxt], AlB[nxt], o + 3, va[i].w);
                    cvt_store(BhB[nxt], BlB[nxt], o + 0, vb[i].x);
                    cvt_store(BhB[nxt], BlB[nxt], o + 1, vb[i].y);
                    cvt_store(BhB[nxt], BlB[nxt], o + 2, vb[i].z);
                    cvt_store(BhB[nxt], BlB[nxt], o + 3, vb[i].w);
                }
            }
            __syncthreads();
        }

        // epilogue: per-warp top3 over its 64 columns for each owned row
        #pragma unroll
        for (int mt = 0; mt < 2; mt++) {
            #pragma unroll
            for (int half = 0; half < 2; half++) {
                int r = wm + mt * 16 + g + half * 8;
                float si = s_si[r];
                float d0 = INFINITY, d1 = INFINITY, d2 = INFINITY;
                int   j0 = 0x7fffffff, j1 = 0x7fffffff, j2 = 0x7fffffff;
                #pragma unroll
                for (int nt = 0; nt < 8; nt++) {
                    int cl = wn + nt * 8 + 2 * t4;
                    float gv0 = acc[mt][nt][half * 2 + 0];
                    float gv1 = acc[mt][nt][half * 2 + 1];
                    float dd0 = sqrtf(fmaxf(si + s_sq[cl]     - 2.f * gv0, 0.f));
                    float dd1 = sqrtf(fmaxf(si + s_sq[cl + 1] - 2.f * gv1, 0.f));
                    top3_insert(dd0, col0 + cl,     d0, j0, d1, j1, d2, j2);
                    top3_insert(dd1, col0 + cl + 1, d0, j0, d1, j1, d2, j2);
                }
                #pragma unroll
                for (int mk = 1; mk <= 2; mk <<= 1) {
                    float e0 = __shfl_xor_sync(0xffffffffu, d0, mk);
                    int   m0 = __shfl_xor_sync(0xffffffffu, j0, mk);
                    float e1 = __shfl_xor_sync(0xffffffffu, d1, mk);
                    int   m1 = __shfl_xor_sync(0xffffffffu, j1, mk);
                    float e2 = __shfl_xor_sync(0xffffffffu, d2, mk);
                    int   m2 = __shfl_xor_sync(0xffffffffu, j2, mk);
                    top3_insert(e0, m0, d0, j0, d1, j1, d2, j2);
                    top3_insert(e1, m1, d0, j0, d1, j1, d2, j2);
                    top3_insert(e2, m2, d0, j0, d1, j1, d2, j2);
                }
                if (t4 == 0) {
                    s_cd[r][warpN][0] = d0; s_cj[r][warpN][0] = j0;
                    s_cd[r][warpN][1] = d1; s_cj[r][warpN][1] = j1;
                    s_cd[r][warpN][2] = d2; s_cj[r][warpN][2] = j2;
                }
            }
        }
        __syncthreads();
        if (tid < 128) {
            float d0 = s_rd[tid][0], d1 = s_rd[tid][1], d2 = s_rd[tid][2];
            int   j0 = s_rj[tid][0], j1 = s_rj[tid][1], j2 = s_rj[tid][2];
            #pragma unroll
            for (int w2 = 0; w2 < 2; w2++)
                #pragma unroll
                for (int e = 0; e < 3; e++)
                    top3_insert(s_cd[tid][w2][e], s_cj[tid][w2][e], d0, j0, d1, j1, d2, j2);
            s_rd[tid][0] = d0; s_rd[tid][1] = d1; s_rd[tid][2] = d2;
            s_rj[tid][0] = j0; s_rj[tid][1] = j1; s_rj[tid][2] = j2;
        }
        __syncthreads();
    }

    if (tid < 128) {
        int row = bNN + row0 + tid;
        int base = (row * NSPLIT + split) * 3;
        g_pd[base + 0] = s_rd[tid][0]; g_pj[base + 0] = s_rj[tid][0];
        g_pd[base + 1] = s_rd[tid][1]; g_pj[base + 1] = s_rj[tid][1];
        g_pd[base + 2] = s_rd[tid][2]; g_pj[base + 2] = s_rj[tid][2];
    }
}

__global__ void adj_kernel() {
    int row = blockIdx.x * blockDim.x + threadIdx.x;
    if (row >= BN) return;
    int i = row % NN;
    float d0 = INFINITY, d1 = INFINITY, d2 = INFINITY;
    int   j0 = 0x7fffffff, j1 = 0x7fffffff, j2 = 0x7fffffff;
    #pragma unroll
    for (int s = 0; s < NSPLIT; s++) {
        int base = (row * NSPLIT + s) * 3;
        #pragma unroll
        for (int e = 0; e < 3; e++)
            top3_insert(g_pd[base + e], g_pj[base + e], d0, j0, d1, j1, d2, j2);
    }
    int f[3] = { j0, j1, j2 };
    int s0 = g_sidx[i * 3 + 0], s1 = g_sidx[i * 3 + 1], s2 = g_sidx[i * 3 + 2];
    int b = row / NN;
    #pragma unroll
    for (int e = 0; e < 3; e++) {
        if (f[e] == s0 || f[e] == s1 || f[e] == s2) {
            int tgt = b * NN + f[e];
            int pos = atomicAdd(&g_deg[tgt], 1);
            if (pos < MAXDEG) g_src[tgt * MAXDEG + pos] = row;
        }
    }
}

// ---------------------------------------------------------------------------
// Merged QKVS GEMM: 256 threads, warp tile 32x64, hi/lo SMEM tiles.
// grid (16, BN/128). dynamic smem: (4*GA + 4*GB) floats = 75776 B
// ---------------------------------------------------------------------------
#define GB 2176   // 16*136 floats

struct GemmArgs {
    const float* A;
    const float* W[4];
    const float* bias[4];
    float* out[4];
};

__global__ void __launch_bounds__(256, 2) gemm_qkvs_kernel(GemmArgs args) {
    extern __shared__ float sm[];
    float* AhB[2] = { sm + 0 * GA, sm + 1 * GA };
    float* AlB[2] = { sm + 2 * GA, sm + 3 * GA };
    float* BhB[2] = { sm + 4 * GA + 0 * GB, sm + 4 * GA + 1 * GB };
    float* BlB[2] = { sm + 4 * GA + 2 * GB, sm + 4 * GA + 3 * GB };

    int wsel = blockIdx.x >> 2;
    int col0 = (blockIdx.x & 3) << 7;
    int row0 = blockIdx.y * 128;
    const float* A = args.A;
    const float* W = args.W[wsel];
    const float* bias = args.bias[wsel];
    float* out = args.out[wsel];

    int tid = threadIdx.x;
    int warp = tid >> 5, lane = tid & 31;
    int wm = (warp >> 1) * 32;
    int wn = (warp & 1) * 64;
    int g = lane >> 2, t4 = lane & 3;

    int m_ld = tid >> 2, k4_ld = (tid & 3) << 2;    // A copies: rows m, m+64
    int k_ld = tid >> 5, n4_ld = (tid & 31) << 2;   // B copies: rows k, k+8

    // prologue buffer 0
    #pragma unroll
    for (int i = 0; i < 2; i++) {
        int m = m_ld + 64 * i;
        int o = m * 20 + k4_ld;
        float4 va = *(const float4*)(A + (size_t)(row0 + m) * CC + k4_ld);
        cvt_store(AhB[0], AlB[0], o + 0, va.x); cvt_store(AhB[0], AlB[0], o + 1, va.y);
        cvt_store(AhB[0], AlB[0], o + 2, va.z); cvt_store(AhB[0], AlB[0], o + 3, va.w);
        int k = k_ld + 8 * i;
        int ob = k * 136 + n4_ld;
        float4 vb = *(const float4*)(W + (size_t)k * CC + col0 + n4_ld);
        cvt_store(BhB[0], BlB[0], ob + 0, vb.x); cvt_store(BhB[0], BlB[0], ob + 1, vb.y);
        cvt_store(BhB[0], BlB[0], ob + 2, vb.z); cvt_store(BhB[0], BlB[0], ob + 3, vb.w);
    }
    __syncthreads();

    float acc[2][8][4] = {};
    for (int k0 = 0; k0 < CC; k0 += 16) {
        int cur = (k0 >> 4) & 1;
        bool hasnext = (k0 + 16 < CC);
        float4 va[2], vb[2];
        if (hasnext) {
            #pragma unroll
            for (int i = 0; i < 2; i++) {
                int m = m_ld + 64 * i;
                va[i] = *(const float4*)(A + (size_t)(row0 + m) * CC + k0 + 16 + k4_ld);
                int k = k0 + 16 + k_ld + 8 * i;
                vb[i] = *(const float4*)(W + (size_t)k * CC + col0 + n4_ld);
            }
        }
        const float* Ah = AhB[cur]; const float* Al = AlB[cur];
        const float* Bh = BhB[cur]; const float* Bl = BlB[cur];
        #pragma unroll
        for (int kk = 0; kk < 16; kk += 8) {
            uint32_t ah[2][4], al[2][4];
            #pragma unroll
            for (int mt = 0; mt < 2; mt++) {
                int r0i = (wm + mt * 16 + g) * 20 + kk + t4;
                int r1i = r0i + 8 * 20;
                ah[mt][0] = __float_as_uint(Ah[r0i]);
                ah[mt][1] = __float_as_uint(Ah[r1i]);
                ah[mt][2] = __float_as_uint(Ah[r0i + 4]);
                ah[mt][3] = __float_as_uint(Ah[r1i + 4]);
                al[mt][0] = __float_as_uint(Al[r0i]);
                al[mt][1] = __float_as_uint(Al[r1i]);
                al[mt][2] = __float_as_uint(Al[r0i + 4]);
                al[mt][3] = __float_as_uint(Al[r1i + 4]);
            }
            #pragma unroll
            for (int nt = 0; nt < 8; nt++) {
                int nc = wn + nt * 8 + g;
                int kb = (kk + t4) * 136 + nc;
                uint32_t bh0 = __float_as_uint(Bh[kb]);
                uint32_t bh1 = __float_as_uint(Bh[kb + 4 * 136]);
                uint32_t bl0 = __float_as_uint(Bl[kb]);
                uint32_t bl1 = __float_as_uint(Bl[kb + 4 * 136]);
                #pragma unroll
                for (int mt = 0; mt < 2; mt++)
                    mma3(acc[mt][nt], ah[mt], al[mt], bh0, bh1, bl0, bl1);
            }
        }
        if (hasnext) {
            int nxt = cur ^ 1;
            #pragma unroll
            for (int i = 0; i < 2; i++) {
                int o = (m_ld + 64 * i) * 20 + k4_ld;
                cvt_store(AhB[nxt], AlB[nxt], o + 0, va[i].x);
                cvt_store(AhB[nxt], AlB[nxt], o + 1, va[i].y);
                cvt_store(AhB[nxt], AlB[nxt], o + 2, va[i].z);
                cvt_store(AhB[nxt], AlB[nxt], o + 3, va[i].w);
                int ob = (k_ld + 8 * i) * 136 + n4_ld;
                cvt_store(BhB[nxt], BlB[nxt], ob + 0, vb[i].x);
                cvt_store(BhB[nxt], BlB[nxt], ob + 1, vb[i].y);
                cvt_store(BhB[nxt], BlB[nxt], ob + 2, vb[i].z);
                cvt_store(BhB[nxt], BlB[nxt], ob + 3, vb[i].w);
            }
        }
        __syncthreads();
    }

    #pragma unroll
    for (int mt = 0; mt < 2; mt++) {
        int r = row0 + wm + mt * 16 + g;
        #pragma unroll
        for (int nt = 0; nt < 8; nt++) {
            int c = col0 + wn + nt * 8 + 2 * t4;
            float b0v = bias[c], b1v = bias[c + 1];
            out[(size_t)r * CC + c]           = acc[mt][nt][0] + b0v;
            out[(size_t)r * CC + c + 1]       = acc[mt][nt][1] + b1v;
            out[(size_t)(r + 8) * CC + c]     = acc[mt][nt][2] + b0v;
            out[(size_t)(r + 8) * CC + c + 1] = acc[mt][nt][3] + b1v;
        }
    }
}

// ---------------------------------------------------------------------------
// sparse attention + skip; one block (128 threads) per target row
// ---------------------------------------------------------------------------
__global__ void attn1_kernel(const float* __restrict__ ln_g,
                             const float* __restrict__ ln_b) {
    int t = blockIdx.x;
    int tid = threadIdx.x, lane = tid & 31, w = tid >> 5;
    __shared__ float s_alpha[MAXDEG];
    __shared__ int   s_srcl[MAXDEG];
    __shared__ float red[128];
    int d = g_deg[t]; if (d > MAXDEG) d = MAXDEG;
    if (tid < d) s_srcl[tid] = g_src[t * MAXDEG + tid];
    __syncthreads();
    const float* qt = g_q + (size_t)t * CC;
    for (int e = w; e < d; e += 4) {
        const float* ks = g_k + (size_t)s_srcl[e] * CC;
        float p = 0.f;
        for (int c = lane; c < CC; c += 32) p += qt[c] * ks[c];
        #pragma unroll
        for (int off = 16; off; off >>= 1) p += __shfl_xor_sync(0xffffffffu, p, off);
        if (lane == 0) s_alpha[e] = p * SCALE;
    }
    __syncthreads();
    if (tid == 0) {
        float mx = -INFINITY;
        for (int e = 0; e < d; e++) mx = fmaxf(mx, s_alpha[e]);
        float sum = 0.f;
        for (int e = 0; e < d; e++) { float ex = expf(s_alpha[e] - mx); s_alpha[e] = ex; sum += ex; }
        float inv = 1.f / sum;
        for (int e = 0; e < d; e++) s_alpha[e] *= inv;
    }
    __syncthreads();
    float ov[4];
    #pragma unroll
    for (int r = 0; r < 4; r++) {
        int c = tid + 128 * r;
        float acc = g_sk[(size_t)t * CC + c];
        for (int e = 0; e < d; e++)
            acc += s_alpha[e] * g_v[(size_t)s_srcl[e] * CC + c];
        ov[r] = fmaxf(acc, 0.f);
    }
    float ls = ov[0] + ov[1] + ov[2] + ov[3];
    float ls2 = ov[0]*ov[0] + ov[1]*ov[1] + ov[2]*ov[2] + ov[3]*ov[3];
    red[tid] = ls; __syncthreads();
    for (int off = 64; off; off >>= 1) { if (tid < off) red[tid] += red[tid + off]; __syncthreads(); }
    float S = red[0]; __syncthreads();
    red[tid] = ls2; __syncthreads();
    for (int off = 64; off; off >>= 1) { if (tid < off) red[tid] += red[tid + off]; __syncthreads(); }
    float S2 = red[0]; __syncthreads();
    float mu  = S * (1.f / CC);
    float var = S2 * (1.f / CC) - mu * mu;
    float inv = rsqrtf(var + LN_EPS);
    #pragma unroll
    for (int r = 0; r < 4; r++) {
        int c = tid + 128 * r;
        g_h1[(size_t)t * CC + c] = (ov[r] - mu) * inv * ln_g[c] + ln_b[c];
    }
}

__global__ void attn2_kernel(const float* __restrict__ x3,
                             float* __restrict__ out) {
    int t = blockIdx.x;
    int tid = threadIdx.x, lane = tid & 31, w = tid >> 5;
    __shared__ float s_alpha[MAXDEG];
    __shared__ int   s_srcl[MAXDEG];
    int d = g_deg[t]; if (d > MAXDEG) d = MAXDEG;
    if (tid < d) s_srcl[tid] = g_src[t * MAXDEG + tid];
    __syncthreads();
    const float* qt = g_q + (size_t)t * CC;
    for (int e = w; e < d; e += 4) {
        const float* ks = g_k + (size_t)s_srcl[e] * CC;
        float p = 0.f;
        for (int c = lane; c < CC; c += 32) p += qt[c] * ks[c];
        #pragma unroll
        for (int off = 16; off; off >>= 1) p += __shfl_xor_sync(0xffffffffu, p, off);
        if (lane == 0) s_alpha[e] = p * SCALE;
    }
    __syncthreads();
    if (tid == 0) {
        float mx = -INFINITY;
        for (int e = 0; e < d; e++) mx = fmaxf(mx, s_alpha[e]);
        float sum = 0.f;
        for (int e = 0; e < d; e++) { float ex = expf(s_alpha[e] - mx); s_alpha[e] = ex; sum += ex; }
        float inv = 1.f / sum;
        for (int e = 0; e < d; e++) s_alpha[e] *= inv;
    }
    __syncthreads();
    #pragma unroll
    for (int r = 0; r < 4; r++) {
        int c = tid + 128 * r;
        size_t idx = (size_t)t * CC + c;
        float acc = g_sk[idx];
        for (int e = 0; e < d; e++)
            acc += s_alpha[e] * g_v[(size_t)s_srcl[e] * CC + c];
        float sig = 1.f / (1.f + expf(-acc));
        out[idx] = x3[idx] * sig;
    }
}

// ---------------------------------------------------------------------------
// launch
// ---------------------------------------------------------------------------
extern "C" void kernel_launch(void* const* d_in, const int* in_sizes, int n_in,
                              void* d_out, int out_size) {
    const float* x3  = (const float*)d_in[0];
    const float* wq1 = (const float*)d_in[1];  const float* bq1 = (const float*)d_in[2];
    const float* wk1 = (const float*)d_in[3];  const float* bk1 = (const float*)d_in[4];
    const float* wv1 = (const float*)d_in[5];  const float* bv1 = (const float*)d_in[6];
    const float* ws1 = (const float*)d_in[7];  const float* bs1 = (const float*)d_in[8];
    const float* wq2 = (const float*)d_in[9];  const float* bq2 = (const float*)d_in[10];
    const float* wk2 = (const float*)d_in[11]; const float* bk2 = (const float*)d_in[12];
    const float* wv2 = (const float*)d_in[13]; const float* bv2 = (const float*)d_in[14];
    const float* ws2 = (const float*)d_in[15]; const float* bs2 = (const float*)d_in[16];
    const float* lng = (const float*)d_in[17]; const float* lnb = (const float*)d_in[18];
    float* out = (float*)d_out;

    float *pq, *pk, *pv, *psk, *ph1;
    cudaGetSymbolAddress((void**)&pq,  g_q);
    cudaGetSymbolAddress((void**)&pk,  g_k);
    cudaGetSymbolAddress((void**)&pv,  g_v);
    cudaGetSymbolAddress((void**)&psk, g_sk);
    cudaGetSymbolAddress((void**)&ph1, g_h1);

    const int GRAM_SMEM = 8 * GA * 4;            // 81920 B
    const int GEMM_SMEM = (4 * GA + 4 * GB) * 4; // 75776 B
    cudaFuncSetAttribute(gram_topk_kernel,
                         cudaFuncAttributeMaxDynamicSharedMemorySize, GRAM_SMEM);
    cudaFuncSetAttribute(gemm_qkvs_kernel,
                         cudaFuncAttributeMaxDynamicSharedMemorySize, GEMM_SMEM);

    // --- graph construction ---
    zero_deg_kernel<<<(BN + 255) / 256, 256>>>();
    ssq_kernel<<<BN / 8, 256>>>(x3);
    spatial_topk_kernel<<<(NN + 255) / 256, 256>>>();
    gram_topk_kernel<<<dim3(NSPLIT, NN / 128, BATCH), 256, GRAM_SMEM>>>(x3);
    adj_kernel<<<(BN + 255) / 256, 256>>>();

    dim3 ggrid(16, BN / 128);

    // --- conv1 ---
    GemmArgs a1;
    a1.A = x3;
    a1.W[0] = wq1; a1.W[1] = wk1; a1.W[2] = wv1; a1.W[3] = ws1;
    a1.bias[0] = bq1; a1.bias[1] = bk1; a1.bias[2] = bv1; a1.bias[3] = bs1;
    a1.out[0] = pq; a1.out[1] = pk; a1.out[2] = pv; a1.out[3] = psk;
    gemm_qkvs_kernel<<<ggrid, 256, GEMM_SMEM>>>(a1);
    attn1_kernel<<<BN, 128>>>(lng, lnb);

    // --- conv2 ---
    GemmArgs a2;
    a2.A = ph1;
    a2.W[0] = wq2; a2.W[1] = wk2; a2.W[2] = wv2; a2.W[3] = ws2;
    a2.bias[0] = bq2; a2.bias[1] = bk2; a2.bias[2] = bv2; a2.bias[3] = bs2;
    a2.out[0] = pq; a2.out[1] = pk; a2.out[2] = pv; a2.out[3] = psk;
    gemm_qkvs_kernel<<<ggrid, 256, GEMM_SMEM>>>(a2);
    attn2_kernel<<<BN, 128>>>(x3, out);
}

// round 13
// speedup vs baseline: 1.3313x; 1.3313x over previous
// VGG16_FPN — R13: gram = R11 (3xtf32, exact kNN); GEMMs = bf16x3 packed-SMEM
// (mma.m16n8k16.bf16, 2x less tensor work, half SMEM traffic).
#include <cuda_runtime.h>
#include <math.h>
#include <stdint.h>

#define BATCH   8
#define CC      512
#define HW      48
#define NN      2304
#define BN      (BATCH * NN)
#define MAXDEG  12
#define SCALE   0.044194173824159216f
#define LN_EPS  1e-5f
#define NSPLIT  2
#define CPS     (NN / NSPLIT)

__device__ float g_ssq [BN];
__device__ int   g_sidx[NN * 3];
__device__ int   g_deg [BN];
__device__ int   g_src [BN * MAXDEG];
__device__ float g_pd  [BN * NSPLIT * 3];
__device__ int   g_pj  [BN * NSPLIT * 3];
__device__ float g_q   [(size_t)BN * CC];
__device__ float g_k   [(size_t)BN * CC];
__device__ float g_v   [(size_t)BN * CC];
__device__ float g_sk  [(size_t)BN * CC];
__device__ float g_h1  [(size_t)BN * CC];

// ---------------- tf32 helpers (gram) ----------------
__device__ __forceinline__ uint32_t f2tf32(float x) {
    uint32_t r;
    asm("cvt.rna.tf32.f32 %0, %1;" : "=r"(r) : "f"(x));
    return r;
}

__device__ __forceinline__ void split_tf32(float v, uint32_t& hi, uint32_t& lo) {
    hi = f2tf32(v);
    lo = f2tf32(v - __uint_as_float(hi));
}

__device__ __forceinline__ void cp_async16(const void* smem_dst, const void* gptr) {
    uint32_t sa = (uint32_t)__cvta_generic_to_shared(smem_dst);
    asm volatile("cp.async.ca.shared.global [%0], [%1], 16;" :: "r"(sa), "l"(gptr));
}

#define CP_COMMIT() asm volatile("cp.async.commit_group;")
#define CP_WAIT(n)  asm volatile("cp.async.wait_group %0;" :: "n"(n))

__device__ __forceinline__ void mma8(float* c, const uint32_t* a,
                                     uint32_t b0, uint32_t b1) {
    asm volatile(
        "mma.sync.aligned.m16n8k8.row.col.f32.tf32.tf32.f32 "
        "{%0,%1,%2,%3},{%4,%5,%6,%7},{%8,%9},{%0,%1,%2,%3};"
        : "+f"(c[0]), "+f"(c[1]), "+f"(c[2]), "+f"(c[3])
        : "r"(a[0]), "r"(a[1]), "r"(a[2]), "r"(a[3]), "r"(b0), "r"(b1));
}

__device__ __forceinline__ void mma3(float* c,
                                     const uint32_t* ah, const uint32_t* al,
                                     uint32_t bh0, uint32_t bh1,
                                     uint32_t bl0, uint32_t bl1) {
    mma8(c, ah, bh0, bh1);
    mma8(c, ah, bl0, bl1);
    mma8(c, al, bh0, bh1);
}

// ---------------- bf16 helpers (gemm) ----------------
// pack (v0 -> low half, v1 -> high half) as bf16x2 (rn), plus residual pack
__device__ __forceinline__ void pack_bf(float v0, float v1,
                                        uint32_t& h, uint32_t& l) {
    uint32_t hh;
    asm("cvt.rn.bf16x2.f32 %0, %1, %2;" : "=r"(hh) : "f"(v1), "f"(v0));
    h = hh;
    float f0 = __uint_as_float(hh << 16);
    float f1 = __uint_as_float(hh & 0xffff0000u);
    asm("cvt.rn.bf16x2.f32 %0, %1, %2;" : "=r"(l) : "f"(v1 - f1), "f"(v0 - f0));
}

__device__ __forceinline__ void mma16bf(float* c, const uint32_t* a,
                                        uint32_t b0, uint32_t b1) {
    asm volatile(
        "mma.sync.aligned.m16n8k16.row.col.f32.bf16.bf16.f32 "
        "{%0,%1,%2,%3},{%4,%5,%6,%7},{%8,%9},{%0,%1,%2,%3};"
        : "+f"(c[0]), "+f"(c[1]), "+f"(c[2]), "+f"(c[3])
        : "r"(a[0]), "r"(a[1]), "r"(a[2]), "r"(a[3]), "r"(b0), "r"(b1));
}

// ---------------- top3 ----------------
__device__ __forceinline__ void top3_insert(float d, int j,
                                            float& d0, int& j0,
                                            float& d1, int& j1,
                                            float& d2, int& j2) {
    bool b2 = (d < d2) || (d == d2 && j < j2);
    if (!b2) return;
    bool b1 = (d < d1) || (d == d1 && j < j1);
    if (b1) {
        d2 = d1; j2 = j1;
        bool b0 = (d < d0) || (d == d0 && j < j0);
        if (b0) { d1 = d0; j1 = j0; d0 = d; j0 = j; }
        else    { d1 = d;  j1 = j; }
    } else {
        d2 = d; j2 = j;
    }
}

__global__ void zero_deg_kernel() {
    int i = blockIdx.x * blockDim.x + threadIdx.x;
    if (i < BN) g_deg[i] = 0;
}

__global__ void ssq_kernel(const float* __restrict__ x) {
    int warp = (blockIdx.x * blockDim.x + threadIdx.x) >> 5;
    int lane = threadIdx.x & 31;
    if (warp >= BN) return;
    const float* row = x + (size_t)warp * CC;
    float s = 0.f;
    for (int c = lane; c < CC; c += 32) { float v = row[c]; s += v * v; }
    #pragma unroll
    for (int off = 16; off; off >>= 1) s += __shfl_xor_sync(0xffffffffu, s, off);
    if (lane == 0) g_ssq[warp] = s;
}

__global__ void spatial_topk_kernel() {
    int i = blockIdx.x * blockDim.x + threadIdx.x;
    if (i >= NN) return;
    int yi = i / HW, xi = i % HW;
    float d0 = INFINITY, d1 = INFINITY, d2 = INFINITY;
    int   j0 = 0x7fffffff, j1 = 0x7fffffff, j2 = 0x7fffffff;
    for (int j = 0; j < NN; j++) {
        int yj = j / HW, xj = j % HW;
        int dy = yi - yj, dx = xi - xj;
        float d = sqrtf((float)(dy * dy + dx * dx));
        top3_insert(d, j, d0, j0, d1, j1, d2, j2);
    }
    g_sidx[i * 3 + 0] = j0;
    g_sidx[i * 3 + 1] = j1;
    g_sidx[i * 3 + 2] = j2;
}

// ---------------------------------------------------------------------------
// Fused Gram + feature-topk (identical to R11): 256 threads, warp tile 32x64,
// fp32 SMEM via cp.async, tf32 split at fragment load.
// dynamic smem: 4 * 2560 floats = 40960 B
// ---------------------------------------------------------------------------
#define GA 2560

__global__ void __launch_bounds__(256, 2) gram_topk_kernel(const float* __restrict__ X) {
    extern __shared__ float sm[];
    float* AsB[2] = { sm + 0 * GA, sm + 1 * GA };
    float* BsB[2] = { sm + 2 * GA, sm + 3 * GA };

    __shared__ float s_rd[128][3];
    __shared__ int   s_rj[128][3];
    __shared__ float s_cd[128][2][3];
    __shared__ int   s_cj[128][2][3];
    __shared__ float s_sq[128];
    __shared__ float s_si[128];

    int split = blockIdx.x;
    int row0  = blockIdx.y * 128;
    int b     = blockIdx.z;
    const float* Xb = X + (size_t)b * NN * CC;
    int bNN = b * NN;

    int tid = threadIdx.x;
    int warp = tid >> 5, lane = tid & 31;
    int wm = (warp >> 1) * 32;
    int wn = (warp & 1) * 64;
    int g = lane >> 2, t4 = lane & 3;
    int warpN = (warp & 1);

    if (tid < 128) {
        s_rd[tid][0] = INFINITY; s_rd[tid][1] = INFINITY; s_rd[tid][2] = INFINITY;
        s_rj[tid][0] = 0x7fffffff; s_rj[tid][1] = 0x7fffffff; s_rj[tid][2] = 0x7fffffff;
        s_si[tid] = g_ssq[bNN + row0 + tid];
    }

    int m_ld  = tid >> 2;
    int k4_ld = (tid & 3) << 2;

    for (int ct = 0; ct < CPS / 128; ct++) {
        int col0 = split * CPS + ct * 128;
        if (tid < 128) s_sq[tid] = g_ssq[bNN + col0 + tid];

        #pragma unroll
        for (int i = 0; i < 2; i++) {
            int m = m_ld + 64 * i;
            int o = m * 20 + k4_ld;
            cp_async16(AsB[0] + o, Xb + (size_t)(row0 + m) * CC + k4_ld);
            cp_async16(BsB[0] + o, Xb + (size_t)(col0 + m) * CC + k4_ld);
        }
        CP_COMMIT();

        float acc[2][8][4] = {};
        for (int k0 = 0; k0 < CC; k0 += 16) {
            int cur = (k0 >> 4) & 1;
            int nxt = cur ^ 1;
            bool hasnext = (k0 + 16 < CC);
            if (hasnext) {
                #pragma unroll
                for (int i = 0; i < 2; i++) {
                    int m = m_ld + 64 * i;
                    int o = m * 20 + k4_ld;
                    cp_async16(AsB[nxt] + o, Xb + (size_t)(row0 + m) * CC + k0 + 16 + k4_ld);
                    cp_async16(BsB[nxt] + o, Xb + (size_t)(col0 + m) * CC + k0 + 16 + k4_ld);
                }
                CP_COMMIT();
                CP_WAIT(1);
            } else {
                CP_WAIT(0);
            }
            __syncthreads();

            const float* As = AsB[cur];
            const float* Bs = BsB[cur];
            #pragma unroll
            for (int kk = 0; kk < 16; kk += 8) {
                uint32_t ah[2][4], al[2][4];
                #pragma unroll
                for (int mt = 0; mt < 2; mt++) {
                    int r0i = (wm + mt * 16 + g) * 20 + kk + t4;
                    int r1i = r0i + 8 * 20;
                    split_tf32(As[r0i],     ah[mt][0], al[mt][0]);
                    split_tf32(As[r1i],     ah[mt][1], al[mt][1]);
                    split_tf32(As[r0i + 4], ah[mt][2], al[mt][2]);
                    split_tf32(As[r1i + 4], ah[mt][3], al[mt][3]);
                }
                #pragma unroll
                for (int nt = 0; nt < 8; nt++) {
                    int nb = (wn + nt * 8 + g) * 20 + kk + t4;
                    uint32_t bh0, bl0, bh1, bl1;
                    split_tf32(Bs[nb],     bh0, bl0);
                    split_tf32(Bs[nb + 4], bh1, bl1);
                    #pragma unroll
                    for (int mt = 0; mt < 2; mt++)
                        mma3(acc[mt][nt], ah[mt], al[mt], bh0, bh1, bl0, bl1);
                }
            }
            __syncthreads();
        }

        #pragma unroll
        for (int mt = 0; mt < 2; mt++) {
            #pragma unroll
            for (int half = 0; half < 2; half++) {
                int r = wm + mt * 16 + g + half * 8;
                float si = s_si[r];
                float d0 = INFINITY, d1 = INFINITY, d2 = INFINITY;
                int   j0 = 0x7fffffff, j1 = 0x7fffffff, j2 = 0x7fffffff;
                #pragma unroll
                for (int nt = 0; nt < 8; nt++) {
                    int cl = wn + nt * 8 + 2 * t4;
                    float gv0 = acc[mt][nt][half * 2 + 0];
                    float gv1 = acc[mt][nt][half * 2 + 1];
                    float dd0 = sqrtf(fmaxf(si + s_sq[cl]     - 2.f * gv0, 0.f));
                    float dd1 = sqrtf(fmaxf(si + s_sq[cl + 1] - 2.f * gv1, 0.f));
                    top3_insert(dd0, col0 + cl,     d0, j0, d1, j1, d2, j2);
                    top3_insert(dd1, col0 + cl + 1, d0, j0, d1, j1, d2, j2);
                }
                #pragma unroll
                for (int mk = 1; mk <= 2; mk <<= 1) {
                    float e0 = __shfl_xor_sync(0xffffffffu, d0, mk);
                    int   m0 = __shfl_xor_sync(0xffffffffu, j0, mk);
                    float e1 = __shfl_xor_sync(0xffffffffu, d1, mk);
                    int   m1 = __shfl_xor_sync(0xffffffffu, j1, mk);
                    float e2 = __shfl_xor_sync(0xffffffffu, d2, mk);
                    int   m2 = __shfl_xor_sync(0xffffffffu, j2, mk);
                    top3_insert(e0, m0, d0, j0, d1, j1, d2, j2);
                    top3_insert(e1, m1, d0, j0, d1, j1, d2, j2);
                    top3_insert(e2, m2, d0, j0, d1, j1, d2, j2);
                }
                if (t4 == 0) {
                    s_cd[r][warpN][0] = d0; s_cj[r][warpN][0] = j0;
                    s_cd[r][warpN][1] = d1; s_cj[r][warpN][1] = j1;
                    s_cd[r][warpN][2] = d2; s_cj[r][warpN][2] = j2;
                }
            }
        }
        __syncthreads();
        if (tid < 128) {
            float d0 = s_rd[tid][0], d1 = s_rd[tid][1], d2 = s_rd[tid][2];
            int   j0 = s_rj[tid][0], j1 = s_rj[tid][1], j2 = s_rj[tid][2];
            #pragma unroll
            for (int w2 = 0; w2 < 2; w2++)
                #pragma unroll
                for (int e = 0; e < 3; e++)
                    top3_insert(s_cd[tid][w2][e], s_cj[tid][w2][e], d0, j0, d1, j1, d2, j2);
            s_rd[tid][0] = d0; s_rd[tid][1] = d1; s_rd[tid][2] = d2;
            s_rj[tid][0] = j0; s_rj[tid][1] = j1; s_rj[tid][2] = j2;
        }
        __syncthreads();
    }

    if (tid < 128) {
        int row = bNN + row0 + tid;
        int base = (row * NSPLIT + split) * 3;
        g_pd[base + 0] = s_rd[tid][0]; g_pj[base + 0] = s_rj[tid][0];
        g_pd[base + 1] = s_rd[tid][1]; g_pj[base + 1] = s_rj[tid][1];
        g_pd[base + 2] = s_rd[tid][2]; g_pj[base + 2] = s_rj[tid][2];
    }
}

__global__ void adj_kernel() {
    int row = blockIdx.x * blockDim.x + threadIdx.x;
    if (row >= BN) return;
    int i = row % NN;
    float d0 = INFINITY, d1 = INFINITY, d2 = INFINITY;
    int   j0 = 0x7fffffff, j1 = 0x7fffffff, j2 = 0x7fffffff;
    #pragma unroll
    for (int s = 0; s < NSPLIT; s++) {
        int base = (row * NSPLIT + s) * 3;
        #pragma unroll
        for (int e = 0; e < 3; e++)
            top3_insert(g_pd[base + e], g_pj[base + e], d0, j0, d1, j1, d2, j2);
    }
    int f[3] = { j0, j1, j2 };
    int s0 = g_sidx[i * 3 + 0], s1 = g_sidx[i * 3 + 1], s2 = g_sidx[i * 3 + 2];
    int b = row / NN;
    #pragma unroll
    for (int e = 0; e < 3; e++) {
        if (f[e] == s0 || f[e] == s1 || f[e] == s2) {
            int tgt = b * NN + f[e];
            int pos = atomicAdd(&g_deg[tgt], 1);
            if (pos < MAXDEG) g_src[tgt * MAXDEG + pos] = row;
        }
    }
}

// ---------------------------------------------------------------------------
// Merged QKVS GEMM — bf16x3. 256 threads, warp tile 32x64, k-step 16.
// SMEM holds PACKED bf16x2 hi/lo operands (split once at copy time):
//   A: [128 rows][12 u32]  (8 k-pairs + 4 pad)   bank = 12g+t4 (conflict-free)
//   B: [8 k-pair rows][136 u32] (128 n + 8 pad)  bank = 8t4+g  (conflict-free)
// dynamic smem: 2 buffers * (2*128*12 + 2*8*136) u32 = 41984 B
// ---------------------------------------------------------------------------
#define PA 12
#define PB 136
#define ASZ (128 * PA)
#define BSZ (8 * PB)

struct GemmArgs {
    const float* A;
    const float* W[4];
    const float* bias[4];
    float* out[4];
};

__global__ void __launch_bounds__(256, 2) gemm_qkvs_kernel(GemmArgs args) {
    extern __shared__ uint32_t smu[];
    uint32_t* AhB[2] = { smu + 0 * ASZ, smu + 1 * ASZ };
    uint32_t* AlB[2] = { smu + 2 * ASZ, smu + 3 * ASZ };
    uint32_t* BhB[2] = { smu + 4 * ASZ + 0 * BSZ, smu + 4 * ASZ + 1 * BSZ };
    uint32_t* BlB[2] = { smu + 4 * ASZ + 2 * BSZ, smu + 4 * ASZ + 3 * BSZ };

    int wsel = blockIdx.x >> 2;
    int col0 = (blockIdx.x & 3) << 7;
    int row0 = blockIdx.y * 128;
    const float* A = args.A;
    const float* W = args.W[wsel];
    const float* bias = args.bias[wsel];
    float* out = args.out[wsel];

    int tid = threadIdx.x;
    int warp = tid >> 5, lane = tid & 31;
    int wm = (warp >> 1) * 32;
    int wn = (warp & 1) * 64;
    int g = lane >> 2, t4 = lane & 3;

    int m_ld = tid >> 2;               // 0..63; rows m, m+64
    int k2_a = (tid & 3) * 2;          // A k-pair base (0,2,4,6)
    int k2_b = tid >> 5;               // 0..7 B k-pair row
    int n4_b = (tid & 31) * 4;         // B col chunk

    // ---- copy+pack one k-tile (16 k) into buffer `buf` for k-origin k0 ----
    auto stage = [&](int buf, int k0) {
        #pragma unroll
        for (int i = 0; i < 2; i++) {
            int m = m_ld + 64 * i;
            float4 va = *(const float4*)(A + (size_t)(row0 + m) * CC + k0 + k2_a * 2);
            uint32_t h0, l0, h1, l1;
            pack_bf(va.x, va.y, h0, l0);
            pack_bf(va.z, va.w, h1, l1);
            int o = m * PA + k2_a;
            AhB[buf][o] = h0; AhB[buf][o + 1] = h1;
            AlB[buf][o] = l0; AlB[buf][o + 1] = l1;
        }
        {
            int k = k0 + 2 * k2_b;
            float4 v0 = *(const float4*)(W + (size_t)k * CC + col0 + n4_b);
            float4 v1 = *(const float4*)(W + (size_t)(k + 1) * CC + col0 + n4_b);
            uint32_t h, l;
            int ob = k2_b * PB + n4_b;
            pack_bf(v0.x, v1.x, h, l); BhB[buf][ob + 0] = h; BlB[buf][ob + 0] = l;
            pack_bf(v0.y, v1.y, h, l); BhB[buf][ob + 1] = h; BlB[buf][ob + 1] = l;
            pack_bf(v0.z, v1.z, h, l); BhB[buf][ob + 2] = h; BlB[buf][ob + 2] = l;
            pack_bf(v0.w, v1.w, h, l); BhB[buf][ob + 3] = h; BlB[buf][ob + 3] = l;
        }
    };

    stage(0, 0);
    __syncthreads();

    float acc[2][8][4] = {};
    for (int k0 = 0; k0 < CC; k0 += 16) {
        int cur = (k0 >> 4) & 1;
        bool hasnext = (k0 + 16 < CC);

        const uint32_t* Ah = AhB[cur]; const uint32_t* Al = AlB[cur];
        const uint32_t* Bh = BhB[cur]; const uint32_t* Bl = BlB[cur];

        uint32_t ah[2][4], al[2][4];
        #pragma unroll
        for (int mt = 0; mt < 2; mt++) {
            int r0 = (wm + mt * 16 + g) * PA;
            int r1 = r0 + 8 * PA;
            ah[mt][0] = Ah[r0 + t4];     al[mt][0] = Al[r0 + t4];
            ah[mt][1] = Ah[r1 + t4];     al[mt][1] = Al[r1 + t4];
            ah[mt][2] = Ah[r0 + t4 + 4]; al[mt][2] = Al[r0 + t4 + 4];
            ah[mt][3] = Ah[r1 + t4 + 4]; al[mt][3] = Al[r1 + t4 + 4];
        }
        #pragma unroll
        for (int nt = 0; nt < 8; nt++) {
            int nc = wn + nt * 8 + g;
            uint32_t bh0 = Bh[t4 * PB + nc];
            uint32_t bh1 = Bh[(t4 + 4) * PB + nc];
            uint32_t bl0 = Bl[t4 * PB + nc];
            uint32_t bl1 = Bl[(t4 + 4) * PB + nc];
            #pragma unroll
            for (int mt = 0; mt < 2; mt++) {
                mma16bf(acc[mt][nt], ah[mt], bh0, bh1);
                mma16bf(acc[mt][nt], ah[mt], bl0, bl1);
                mma16bf(acc[mt][nt], al[mt], bh0, bh1);
            }
        }

        if (hasnext) {
            // stage next tile into the other buffer (reads GMEM, writes SMEM)
            __syncthreads();          // mma phase done reading cur? (cur is only READ; nxt written)
            stage(cur ^ 1, k0 + 16);
        }
        __syncthreads();
    }

    #pragma unroll
    for (int mt = 0; mt < 2; mt++) {
        int r = row0 + wm + mt * 16 + g;
        #pragma unroll
        for (int nt = 0; nt < 8; nt++) {
            int c = col0 + wn + nt * 8 + 2 * t4;
            float b0v = bias[c], b1v = bias[c + 1];
            out[(size_t)r * CC + c]           = acc[mt][nt][0] + b0v;
            out[(size_t)r * CC + c + 1]       = acc[mt][nt][1] + b1v;
            out[(size_t)(r + 8) * CC + c]     = acc[mt][nt][2] + b0v;
            out[(size_t)(r + 8) * CC + c + 1] = acc[mt][nt][3] + b1v;
        }
    }
}

// ---------------------------------------------------------------------------
// sparse attention + skip; one block (128 threads) per target row
// ---------------------------------------------------------------------------
__global__ void attn1_kernel(const float* __restrict__ ln_g,
                             const float* __restrict__ ln_b) {
    int t = blockIdx.x;
    int tid = threadIdx.x, lane = tid & 31, w = tid >> 5;
    __shared__ float s_alpha[MAXDEG];
    __shared__ int   s_srcl[MAXDEG];
    __shared__ float red[128];
    int d = g_deg[t]; if (d > MAXDEG) d = MAXDEG;
    if (tid < d) s_srcl[tid] = g_src[t * MAXDEG + tid];
    __syncthreads();
    const float* qt = g_q + (size_t)t * CC;
    for (int e = w; e < d; e += 4) {
        const float* ks = g_k + (size_t)s_srcl[e] * CC;
        float p = 0.f;
        for (int c = lane; c < CC; c += 32) p += qt[c] * ks[c];
        #pragma unroll
        for (int off = 16; off; off >>= 1) p += __shfl_xor_sync(0xffffffffu, p, off);
        if (lane == 0) s_alpha[e] = p * SCALE;
    }
    __syncthreads();
    if (tid == 0) {
        float mx = -INFINITY;
        for (int e = 0; e < d; e++) mx = fmaxf(mx, s_alpha[e]);
        float sum = 0.f;
        for (int e = 0; e < d; e++) { float ex = expf(s_alpha[e] - mx); s_alpha[e] = ex; sum += ex; }
        float inv = 1.f / sum;
        for (int e = 0; e < d; e++) s_alpha[e] *= inv;
    }
    __syncthreads();
    float ov[4];
    #pragma unroll
    for (int r = 0; r < 4; r++) {
        int c = tid + 128 * r;
        float acc = g_sk[(size_t)t * CC + c];
        for (int e = 0; e < d; e++)
            acc += s_alpha[e] * g_v[(size_t)s_srcl[e] * CC + c];
        ov[r] = fmaxf(acc, 0.f);
    }
    float ls = ov[0] + ov[1] + ov[2] + ov[3];
    float ls2 = ov[0]*ov[0] + ov[1]*ov[1] + ov[2]*ov[2] + ov[3]*ov[3];
    red[tid] = ls; __syncthreads();
    for (int off = 64; off; off >>= 1) { if (tid < off) red[tid] += red[tid + off]; __syncthreads(); }
    float S = red[0]; __syncthreads();
    red[tid] = ls2; __syncthreads();
    for (int off = 64; off; off >>= 1) { if (tid < off) red[tid] += red[tid + off]; __syncthreads(); }
    float S2 = red[0]; __syncthreads();
    float mu  = S * (1.f / CC);
    float var = S2 * (1.f / CC) - mu * mu;
    float inv = rsqrtf(var + LN_EPS);
    #pragma unroll
    for (int r = 0; r < 4; r++) {
        int c = tid + 128 * r;
        g_h1[(size_t)t * CC + c] = (ov[r] - mu) * inv * ln_g[c] + ln_b[c];
    }
}

__global__ void attn2_kernel(const float* __restrict__ x3,
                             float* __restrict__ out) {
    int t = blockIdx.x;
    int tid = threadIdx.x, lane = tid & 31, w = tid >> 5;
    __shared__ float s_alpha[MAXDEG];
    __shared__ int   s_srcl[MAXDEG];
    int d = g_deg[t]; if (d > MAXDEG) d = MAXDEG;
    if (tid < d) s_srcl[tid] = g_src[t * MAXDEG + tid];
    __syncthreads();
    const float* qt = g_q + (size_t)t * CC;
    for (int e = w; e < d; e += 4) {
        const float* ks = g_k + (size_t)s_srcl[e] * CC;
        float p = 0.f;
        for (int c = lane; c < CC; c += 32) p += qt[c] * ks[c];
        #pragma unroll
        for (int off = 16; off; off >>= 1) p += __shfl_xor_sync(0xffffffffu, p, off);
        if (lane == 0) s_alpha[e] = p * SCALE;
    }
    __syncthreads();
    if (tid == 0) {
        float mx = -INFINITY;
        for (int e = 0; e < d; e++) mx = fmaxf(mx, s_alpha[e]);
        float sum = 0.f;
        for (int e = 0; e < d; e++) { float ex = expf(s_alpha[e] - mx); s_alpha[e] = ex; sum += ex; }
        float inv = 1.f / sum;
        for (int e = 0; e < d; e++) s_alpha[e] *= inv;
    }
    __syncthreads();
    #pragma unroll
    for (int r = 0; r < 4; r++) {
        int c = tid + 128 * r;
        size_t idx = (size_t)t * CC + c;
        float acc = g_sk[idx];
        for (int e = 0; e < d; e++)
            acc += s_alpha[e] * g_v[(size_t)s_srcl[e] * CC + c];
        float sig = 1.f / (1.f + expf(-acc));
        out[idx] = x3[idx] * sig;
    }
}

// ---------------------------------------------------------------------------
// launch
// ---------------------------------------------------------------------------
extern "C" void kernel_launch(void* const* d_in, const int* in_sizes, int n_in,
                              void* d_out, int out_size) {
    const float* x3  = (const float*)d_in[0];
    const float* wq1 = (const float*)d_in[1];  const float* bq1 = (const float*)d_in[2];
    const float* wk1 = (const float*)d_in[3];  const float* bk1 = (const float*)d_in[4];
    const float* wv1 = (const float*)d_in[5];  const float* bv1 = (const float*)d_in[6];
    const float* ws1 = (const float*)d_in[7];  const float* bs1 = (const float*)d_in[8];
    const float* wq2 = (const float*)d_in[9];  const float* bq2 = (const float*)d_in[10];
    const float* wk2 = (const float*)d_in[11]; const float* bk2 = (const float*)d_in[12];
    const float* wv2 = (const float*)d_in[13]; const float* bv2 = (const float*)d_in[14];
    const float* ws2 = (const float*)d_in[15]; const float* bs2 = (const float*)d_in[16];
    const float* lng = (const float*)d_in[17]; const float* lnb = (const float*)d_in[18];
    float* out = (float*)d_out;

    float *pq, *pk, *pv, *psk, *ph1;
    cudaGetSymbolAddress((void**)&pq,  g_q);
    cudaGetSymbolAddress((void**)&pk,  g_k);
    cudaGetSymbolAddress((void**)&pv,  g_v);
    cudaGetSymbolAddress((void**)&psk, g_sk);
    cudaGetSymbolAddress((void**)&ph1, g_h1);

    const int GRAM_SMEM = 4 * GA * 4;                       // 40960 B
    const int GEMM_SMEM = (4 * ASZ + 4 * BSZ) * 4;          // 41984 B
    cudaFuncSetAttribute(gram_topk_kernel,
                         cudaFuncAttributeMaxDynamicSharedMemorySize, GRAM_SMEM);
    cudaFuncSetAttribute(gemm_qkvs_kernel,
                         cudaFuncAttributeMaxDynamicSharedMemorySize, GEMM_SMEM);

    // --- graph construction ---
    zero_deg_kernel<<<(BN + 255) / 256, 256>>>();
    ssq_kernel<<<BN / 8, 256>>>(x3);
    spatial_topk_kernel<<<(NN + 255) / 256, 256>>>();
    gram_topk_kernel<<<dim3(NSPLIT, NN / 128, BATCH), 256, GRAM_SMEM>>>(x3);
    adj_kernel<<<(BN + 255) / 256, 256>>>();

    dim3 ggrid(16, BN / 128);

    // --- conv1 ---
    GemmArgs a1;
    a1.A = x3;
    a1.W[0] = wq1; a1.W[1] = wk1; a1.W[2] = wv1; a1.W[3] = ws1;
    a1.bias[0] = bq1; a1.bias[1] = bk1; a1.bias[2] = bv1; a1.bias[3] = bs1;
    a1.out[0] = pq; a1.out[1] = pk; a1.out[2] = pv; a1.out[3] = psk;
    gemm_qkvs_kernel<<<ggrid, 256, GEMM_SMEM>>>(a1);
    attn1_kernel<<<BN, 128>>>(lng, lnb);

    // --- conv2 ---
    GemmArgs a2;
    a2.A = ph1;
    a2.W[0] = wq2; a2.W[1] = wk2; a2.W[2] = wv2; a2.W[3] = ws2;
    a2.bias[0] = bq2; a2.bias[1] = bk2; a2.bias[2] = bv2; a2.bias[3] = bs2;
    a2.out[0] = pq; a2.out[1] = pk; a2.out[2] = pv; a2.out[3] = psk;
    gemm_qkvs_kernel<<<ggrid, 256, GEMM_SMEM>>>(a2);
    attn2_kernel<<<BN, 128>>>(x3, out);
}

// round 14
// speedup vs baseline: 1.4698x; 1.1041x over previous
// VGG16_FPN — R14: symmetric gram (171/324 tiles, row+col top3 epilogue),
// bf16x3 GEMMs (R13), 3xtf32 exact kNN distances.
#include <cuda_runtime.h>
#include <math.h>
#include <stdint.h>

#define BATCH   8
#define CC      512
#define HW      48
#define NN      2304
#define BN      (BATCH * NN)
#define MAXDEG  12
#define SCALE   0.044194173824159216f
#define LN_EPS  1e-5f
#define NPART   18              // 2304/128 partial top3 slots per row
#define NTILE   171             // 18*19/2 tile pairs per sample

__device__ float g_ssq [BN];
__device__ int   g_sidx[NN * 3];
__device__ int   g_deg [BN];
__device__ int   g_src [BN * MAXDEG];
__device__ float g_pd  [(size_t)BN * NPART * 3];
__device__ int   g_pj  [(size_t)BN * NPART * 3];
__device__ float g_q   [(size_t)BN * CC];
__device__ float g_k   [(size_t)BN * CC];
__device__ float g_v   [(size_t)BN * CC];
__device__ float g_sk  [(size_t)BN * CC];
__device__ float g_h1  [(size_t)BN * CC];

// ---------------- tf32 helpers (gram) ----------------
__device__ __forceinline__ uint32_t f2tf32(float x) {
    uint32_t r;
    asm("cvt.rna.tf32.f32 %0, %1;" : "=r"(r) : "f"(x));
    return r;
}

__device__ __forceinline__ void split_tf32(float v, uint32_t& hi, uint32_t& lo) {
    hi = f2tf32(v);
    lo = f2tf32(v - __uint_as_float(hi));
}

__device__ __forceinline__ void cp_async16(const void* smem_dst, const void* gptr) {
    uint32_t sa = (uint32_t)__cvta_generic_to_shared(smem_dst);
    asm volatile("cp.async.ca.shared.global [%0], [%1], 16;" :: "r"(sa), "l"(gptr));
}

#define CP_COMMIT() asm volatile("cp.async.commit_group;")
#define CP_WAIT(n)  asm volatile("cp.async.wait_group %0;" :: "n"(n))

__device__ __forceinline__ void mma8(float* c, const uint32_t* a,
                                     uint32_t b0, uint32_t b1) {
    asm volatile(
        "mma.sync.aligned.m16n8k8.row.col.f32.tf32.tf32.f32 "
        "{%0,%1,%2,%3},{%4,%5,%6,%7},{%8,%9},{%0,%1,%2,%3};"
        : "+f"(c[0]), "+f"(c[1]), "+f"(c[2]), "+f"(c[3])
        : "r"(a[0]), "r"(a[1]), "r"(a[2]), "r"(a[3]), "r"(b0), "r"(b1));
}

__device__ __forceinline__ void mma3(float* c,
                                     const uint32_t* ah, const uint32_t* al,
                                     uint32_t bh0, uint32_t bh1,
                                     uint32_t bl0, uint32_t bl1) {
    mma8(c, ah, bh0, bh1);
    mma8(c, ah, bl0, bl1);
    mma8(c, al, bh0, bh1);
}

// ---------------- bf16 helpers (gemm) ----------------
__device__ __forceinline__ void pack_bf(float v0, float v1,
                                        uint32_t& h, uint32_t& l) {
    uint32_t hh;
    asm("cvt.rn.bf16x2.f32 %0, %1, %2;" : "=r"(hh) : "f"(v1), "f"(v0));
    h = hh;
    float f0 = __uint_as_float(hh << 16);
    float f1 = __uint_as_float(hh & 0xffff0000u);
    asm("cvt.rn.bf16x2.f32 %0, %1, %2;" : "=r"(l) : "f"(v1 - f1), "f"(v0 - f0));
}

__device__ __forceinline__ void mma16bf(float* c, const uint32_t* a,
                                        uint32_t b0, uint32_t b1) {
    asm volatile(
        "mma.sync.aligned.m16n8k16.row.col.f32.bf16.bf16.f32 "
        "{%0,%1,%2,%3},{%4,%5,%6,%7},{%8,%9},{%0,%1,%2,%3};"
        : "+f"(c[0]), "+f"(c[1]), "+f"(c[2]), "+f"(c[3])
        : "r"(a[0]), "r"(a[1]), "r"(a[2]), "r"(a[3]), "r"(b0), "r"(b1));
}

// ---------------- top3 ----------------
__device__ __forceinline__ void top3_insert(float d, int j,
                                            float& d0, int& j0,
                                            float& d1, int& j1,
                                            float& d2, int& j2) {
    bool b2 = (d < d2) || (d == d2 && j < j2);
    if (!b2) return;
    bool b1 = (d < d1) || (d == d1 && j < j1);
    if (b1) {
        d2 = d1; j2 = j1;
        bool b0 = (d < d0) || (d == d0 && j < j0);
        if (b0) { d1 = d0; j1 = j0; d0 = d; j0 = j; }
        else    { d1 = d;  j1 = j; }
    } else {
        d2 = d; j2 = j;
    }
}

__global__ void zero_deg_kernel() {
    int i = blockIdx.x * blockDim.x + threadIdx.x;
    if (i < BN) g_deg[i] = 0;
}

__global__ void ssq_kernel(const float* __restrict__ x) {
    int warp = (blockIdx.x * blockDim.x + threadIdx.x) >> 5;
    int lane = threadIdx.x & 31;
    if (warp >= BN) return;
    const float* row = x + (size_t)warp * CC;
    float s = 0.f;
    for (int c = lane; c < CC; c += 32) { float v = row[c]; s += v * v; }
    #pragma unroll
    for (int off = 16; off; off >>= 1) s += __shfl_xor_sync(0xffffffffu, s, off);
    if (lane == 0) g_ssq[warp] = s;
}

__global__ void spatial_topk_kernel() {
    int i = blockIdx.x * blockDim.x + threadIdx.x;
    if (i >= NN) return;
    int yi = i / HW, xi = i % HW;
    float d0 = INFINITY, d1 = INFINITY, d2 = INFINITY;
    int   j0 = 0x7fffffff, j1 = 0x7fffffff, j2 = 0x7fffffff;
    for (int j = 0; j < NN; j++) {
        int yj = j / HW, xj = j % HW;
        int dy = yi - yj, dx = xi - xj;
        float d = sqrtf((float)(dy * dy + dx * dx));
        top3_insert(d, j, d0, j0, d1, j1, d2, j2);
    }
    g_sidx[i * 3 + 0] = j0;
    g_sidx[i * 3 + 1] = j1;
    g_sidx[i * 3 + 2] = j2;
}

// ---------------------------------------------------------------------------
// Symmetric fused Gram + topk: one block per (bi >= bj) 128x128 tile.
// Row-pass: top3 for rows of stripe bi (slot bj). Col-pass (off-diag only):
// top3 for rows of stripe bj from column reduction (slot bi).
// 256 threads, warp tile 32x64, fp32 SMEM via cp.async, tf32 @ frag load.
// dynamic smem: 4 * 2560 floats = 40960 B
// ---------------------------------------------------------------------------
#define GA 2560

__global__ void __launch_bounds__(256, 2) gram_topk_kernel(const float* __restrict__ X) {
    extern __shared__ float sm[];
    float* AsB[2] = { sm + 0 * GA, sm + 1 * GA };
    float* BsB[2] = { sm + 2 * GA, sm + 3 * GA };

    __shared__ float s_cd[128][2][3];   // row-pass cross-colwarp merge
    __shared__ int   s_cj[128][2][3];
    __shared__ float s_ccd[128][4][3];  // col-pass cross-rowwarp merge
    __shared__ int   s_ccj[128][4][3];
    __shared__ float s_sq[128];         // col stripe ssq
    __shared__ float s_si[128];         // row stripe ssq

    // decode triangular pair index
    int p = blockIdx.x;
    int bi = (int)((sqrtf(8.f * p + 1.f) - 1.f) * 0.5f);
    while ((bi + 1) * (bi + 2) / 2 <= p) bi++;
    while (bi * (bi + 1) / 2 > p) bi--;
    int bj = p - bi * (bi + 1) / 2;
    bool diag = (bi == bj);

    int b = blockIdx.z;
    const float* Xb = X + (size_t)b * NN * CC;
    int bNN = b * NN;
    int row0 = bi * 128, col0 = bj * 128;

    int tid = threadIdx.x;
    int warp = tid >> 5, lane = tid & 31;
    int wm = (warp >> 1) * 32;     // row-group
    int wn = (warp & 1) * 64;      // col-group
    int g = lane >> 2, t4 = lane & 3;
    int warpN = (warp & 1);
    int warpR = (warp >> 1);

    if (tid < 128) {
        s_si[tid] = g_ssq[bNN + row0 + tid];
        s_sq[tid] = g_ssq[bNN + col0 + tid];
    }

    int m_ld  = tid >> 2;
    int k4_ld = (tid & 3) << 2;

    #pragma unroll
    for (int i = 0; i < 2; i++) {
        int m = m_ld + 64 * i;
        int o = m * 20 + k4_ld;
        cp_async16(AsB[0] + o, Xb + (size_t)(row0 + m) * CC + k4_ld);
        cp_async16(BsB[0] + o, Xb + (size_t)(col0 + m) * CC + k4_ld);
    }
    CP_COMMIT();

    float acc[2][8][4] = {};
    for (int k0 = 0; k0 < CC; k0 += 16) {
        int cur = (k0 >> 4) & 1;
        int nxt = cur ^ 1;
        bool hasnext = (k0 + 16 < CC);
        if (hasnext) {
            #pragma unroll
            for (int i = 0; i < 2; i++) {
                int m = m_ld + 64 * i;
                int o = m * 20 + k4_ld;
                cp_async16(AsB[nxt] + o, Xb + (size_t)(row0 + m) * CC + k0 + 16 + k4_ld);
                cp_async16(BsB[nxt] + o, Xb + (size_t)(col0 + m) * CC + k0 + 16 + k4_ld);
            }
            CP_COMMIT();
            CP_WAIT(1);
        } else {
            CP_WAIT(0);
        }
        __syncthreads();

        const float* As = AsB[cur];
        const float* Bs = BsB[cur];
        #pragma unroll
        for (int kk = 0; kk < 16; kk += 8) {
            uint32_t ah[2][4], al[2][4];
            #pragma unroll
            for (int mt = 0; mt < 2; mt++) {
                int r0i = (wm + mt * 16 + g) * 20 + kk + t4;
                int r1i = r0i + 8 * 20;
                split_tf32(As[r0i],     ah[mt][0], al[mt][0]);
                split_tf32(As[r1i],     ah[mt][1], al[mt][1]);
                split_tf32(As[r0i + 4], ah[mt][2], al[mt][2]);
                split_tf32(As[r1i + 4], ah[mt][3], al[mt][3]);
            }
            #pragma unroll
            for (int nt = 0; nt < 8; nt++) {
                int nb = (wn + nt * 8 + g) * 20 + kk + t4;
                uint32_t bh0, bl0, bh1, bl1;
                split_tf32(Bs[nb],     bh0, bl0);
                split_tf32(Bs[nb + 4], bh1, bl1);
                #pragma unroll
                for (int mt = 0; mt < 2; mt++)
                    mma3(acc[mt][nt], ah[mt], al[mt], bh0, bh1, bl0, bl1);
            }
        }
        __syncthreads();
    }

    // -------- row-pass: top3 over tile columns for each row of stripe bi ----
    #pragma unroll
    for (int mt = 0; mt < 2; mt++) {
        #pragma unroll
        for (int half = 0; half < 2; half++) {
            int r = wm + mt * 16 + g + half * 8;
            float si = s_si[r];
            float d0 = INFINITY, d1 = INFINITY, d2 = INFINITY;
            int   j0 = 0x7fffffff, j1 = 0x7fffffff, j2 = 0x7fffffff;
            #pragma unroll
            for (int nt = 0; nt < 8; nt++) {
                int cl = wn + nt * 8 + 2 * t4;
                float gv0 = acc[mt][nt][half * 2 + 0];
                float gv1 = acc[mt][nt][half * 2 + 1];
                float dd0 = sqrtf(fmaxf(si + s_sq[cl]     - 2.f * gv0, 0.f));
                float dd1 = sqrtf(fmaxf(si + s_sq[cl + 1] - 2.f * gv1, 0.f));
                top3_insert(dd0, col0 + cl,     d0, j0, d1, j1, d2, j2);
                top3_insert(dd1, col0 + cl + 1, d0, j0, d1, j1, d2, j2);
            }
            #pragma unroll
            for (int mk = 1; mk <= 2; mk <<= 1) {
                float e0 = __shfl_xor_sync(0xffffffffu, d0, mk);
                int   m0 = __shfl_xor_sync(0xffffffffu, j0, mk);
                float e1 = __shfl_xor_sync(0xffffffffu, d1, mk);
                int   m1 = __shfl_xor_sync(0xffffffffu, j1, mk);
                float e2 = __shfl_xor_sync(0xffffffffu, d2, mk);
                int   m2 = __shfl_xor_sync(0xffffffffu, j2, mk);
                top3_insert(e0, m0, d0, j0, d1, j1, d2, j2);
                top3_insert(e1, m1, d0, j0, d1, j1, d2, j2);
                top3_insert(e2, m2, d0, j0, d1, j1, d2, j2);
            }
            if (t4 == 0) {
                s_cd[r][warpN][0] = d0; s_cj[r][warpN][0] = j0;
                s_cd[r][warpN][1] = d1; s_cj[r][warpN][1] = j1;
                s_cd[r][warpN][2] = d2; s_cj[r][warpN][2] = j2;
            }
        }
    }
    __syncthreads();
    if (tid < 128) {
        float d0 = INFINITY, d1 = INFINITY, d2 = INFINITY;
        int   j0 = 0x7fffffff, j1 = 0x7fffffff, j2 = 0x7fffffff;
        #pragma unroll
        for (int w2 = 0; w2 < 2; w2++)
            #pragma unroll
            for (int e = 0; e < 3; e++)
                top3_insert(s_cd[tid][w2][e], s_cj[tid][w2][e], d0, j0, d1, j1, d2, j2);
        size_t base = ((size_t)(bNN + row0 + tid) * NPART + bj) * 3;
        g_pd[base + 0] = d0; g_pj[base + 0] = j0;
        g_pd[base + 1] = d1; g_pj[base + 1] = j1;
        g_pd[base + 2] = d2; g_pj[base + 2] = j2;
    }

    // -------- col-pass (off-diagonal): top3 over tile rows per column -------
    if (!diag) {
        #pragma unroll
        for (int nt = 0; nt < 8; nt++) {
            #pragma unroll
            for (int cbit = 0; cbit < 2; cbit++) {
                int cl = wn + nt * 8 + 2 * t4 + cbit;
                float sj = s_sq[cl];
                float d0 = INFINITY, d1 = INFINITY, d2 = INFINITY;
                int   j0 = 0x7fffffff, j1 = 0x7fffffff, j2 = 0x7fffffff;
                #pragma unroll
                for (int mt = 0; mt < 2; mt++)
                    #pragma unroll
                    for (int half = 0; half < 2; half++) {
                        int r = wm + mt * 16 + g + half * 8;
                        float gv = acc[mt][nt][half * 2 + cbit];
                        float dd = sqrtf(fmaxf(s_si[r] + sj - 2.f * gv, 0.f));
                        top3_insert(dd, row0 + r, d0, j0, d1, j1, d2, j2);
                    }
                // merge across g (lanes stride 4): masks 4, 8, 16
                #pragma unroll
                for (int mk = 4; mk <= 16; mk <<= 1) {
                    float e0 = __shfl_xor_sync(0xffffffffu, d0, mk);
                    int   m0 = __shfl_xor_sync(0xffffffffu, j0, mk);
                    float e1 = __shfl_xor_sync(0xffffffffu, d1, mk);
                    int   m1 = __shfl_xor_sync(0xffffffffu, j1, mk);
                    float e2 = __shfl_xor_sync(0xffffffffu, d2, mk);
                    int   m2 = __shfl_xor_sync(0xffffffffu, j2, mk);
                    top3_insert(e0, m0, d0, j0, d1, j1, d2, j2);
                    top3_insert(e1, m1, d0, j0, d1, j1, d2, j2);
                    top3_insert(e2, m2, d0, j0, d1, j1, d2, j2);
                }
                if (g == 0) {
                    s_ccd[cl][warpR][0] = d0; s_ccj[cl][warpR][0] = j0;
                    s_ccd[cl][warpR][1] = d1; s_ccj[cl][warpR][1] = j1;
                    s_ccd[cl][warpR][2] = d2; s_ccj[cl][warpR][2] = j2;
                }
            }
        }
        __syncthreads();
        if (tid < 128) {
            float d0 = INFINITY, d1 = INFINITY, d2 = INFINITY;
            int   j0 = 0x7fffffff, j1 = 0x7fffffff, j2 = 0x7fffffff;
            #pragma unroll
            for (int w4 = 0; w4 < 4; w4++)
                #pragma unroll
                for (int e = 0; e < 3; e++)
                    top3_insert(s_ccd[tid][w4][e], s_ccj[tid][w4][e], d0, j0, d1, j1, d2, j2);
            size_t base = ((size_t)(bNN + col0 + tid) * NPART + bi) * 3;
            g_pd[base + 0] = d0; g_pj[base + 0] = j0;
            g_pd[base + 1] = d1; g_pj[base + 1] = j1;
            g_pd[base + 2] = d2; g_pj[base + 2] = j2;
        }
    }
}

// adjacency: merge NPART partials -> feature top3, intersect with spatial top3
__global__ void adj_kernel() {
    int row = blockIdx.x * blockDim.x + threadIdx.x;
    if (row >= BN) return;
    int i = row % NN;
    float d0 = INFINITY, d1 = INFINITY, d2 = INFINITY;
    int   j0 = 0x7fffffff, j1 = 0x7fffffff, j2 = 0x7fffffff;
    size_t base = (size_t)row * NPART * 3;
    for (int s = 0; s < NPART * 3; s++)
        top3_insert(g_pd[base + s], g_pj[base + s], d0, j0, d1, j1, d2, j2);
    int f[3] = { j0, j1, j2 };
    int s0 = g_sidx[i * 3 + 0], s1 = g_sidx[i * 3 + 1], s2 = g_sidx[i * 3 + 2];
    int b = row / NN;
    #pragma unroll
    for (int e = 0; e < 3; e++) {
        if (f[e] == s0 || f[e] == s1 || f[e] == s2) {
            int tgt = b * NN + f[e];
            int pos = atomicAdd(&g_deg[tgt], 1);
            if (pos < MAXDEG) g_src[tgt * MAXDEG + pos] = row;
        }
    }
}

// ---------------------------------------------------------------------------
// Merged QKVS GEMM — bf16x3 (identical to R13).
// ---------------------------------------------------------------------------
#define PA 12
#define PB 136
#define ASZ (128 * PA)
#define BSZ (8 * PB)

struct GemmArgs {
    const float* A;
    const float* W[4];
    const float* bias[4];
    float* out[4];
};

__global__ void __launch_bounds__(256, 2) gemm_qkvs_kernel(GemmArgs args) {
    extern __shared__ uint32_t smu[];
    uint32_t* AhB[2] = { smu + 0 * ASZ, smu + 1 * ASZ };
    uint32_t* AlB[2] = { smu + 2 * ASZ, smu + 3 * ASZ };
    uint32_t* BhB[2] = { smu + 4 * ASZ + 0 * BSZ, smu + 4 * ASZ + 1 * BSZ };
    uint32_t* BlB[2] = { smu + 4 * ASZ + 2 * BSZ, smu + 4 * ASZ + 3 * BSZ };

    int wsel = blockIdx.x >> 2;
    int col0 = (blockIdx.x & 3) << 7;
    int row0 = blockIdx.y * 128;
    const float* A = args.A;
    const float* W = args.W[wsel];
    const float* bias = args.bias[wsel];
    float* out = args.out[wsel];

    int tid = threadIdx.x;
    int warp = tid >> 5, lane = tid & 31;
    int wm = (warp >> 1) * 32;
    int wn = (warp & 1) * 64;
    int g = lane >> 2, t4 = lane & 3;

    int m_ld = tid >> 2;
    int k2_a = (tid & 3) * 2;
    int k2_b = tid >> 5;
    int n4_b = (tid & 31) * 4;

    auto stage = [&](int buf, int k0) {
        #pragma unroll
        for (int i = 0; i < 2; i++) {
            int m = m_ld + 64 * i;
            float4 va = *(const float4*)(A + (size_t)(row0 + m) * CC + k0 + k2_a * 2);
            uint32_t h0, l0, h1, l1;
            pack_bf(va.x, va.y, h0, l0);
            pack_bf(va.z, va.w, h1, l1);
            int o = m * PA + k2_a;
            AhB[buf][o] = h0; AhB[buf][o + 1] = h1;
            AlB[buf][o] = l0; AlB[buf][o + 1] = l1;
        }
        {
            int k = k0 + 2 * k2_b;
            float4 v0 = *(const float4*)(W + (size_t)k * CC + col0 + n4_b);
            float4 v1 = *(const float4*)(W + (size_t)(k + 1) * CC + col0 + n4_b);
            uint32_t h, l;
            int ob = k2_b * PB + n4_b;
            pack_bf(v0.x, v1.x, h, l); BhB[buf][ob + 0] = h; BlB[buf][ob + 0] = l;
            pack_bf(v0.y, v1.y, h, l); BhB[buf][ob + 1] = h; BlB[buf][ob + 1] = l;
            pack_bf(v0.z, v1.z, h, l); BhB[buf][ob + 2] = h; BlB[buf][ob + 2] = l;
            pack_bf(v0.w, v1.w, h, l); BhB[buf][ob + 3] = h; BlB[buf][ob + 3] = l;
        }
    };

    stage(0, 0);
    __syncthreads();

    float acc[2][8][4] = {};
    for (int k0 = 0; k0 < CC; k0 += 16) {
        int cur = (k0 >> 4) & 1;
        bool hasnext = (k0 + 16 < CC);

        const uint32_t* Ah = AhB[cur]; const uint32_t* Al = AlB[cur];
        const uint32_t* Bh = BhB[cur]; const uint32_t* Bl = BlB[cur];

        uint32_t ah[2][4], al[2][4];
        #pragma unroll
        for (int mt = 0; mt < 2; mt++) {
            int r0 = (wm + mt * 16 + g) * PA;
            int r1 = r0 + 8 * PA;
            ah[mt][0] = Ah[r0 + t4];     al[mt][0] = Al[r0 + t4];
            ah[mt][1] = Ah[r1 + t4];     al[mt][1] = Al[r1 + t4];
            ah[mt][2] = Ah[r0 + t4 + 4]; al[mt][2] = Al[r0 + t4 + 4];
            ah[mt][3] = Ah[r1 + t4 + 4]; al[mt][3] = Al[r1 + t4 + 4];
        }
        #pragma unroll
        for (int nt = 0; nt < 8; nt++) {
            int nc = wn + nt * 8 + g;
            uint32_t bh0 = Bh[t4 * PB + nc];
            uint32_t bh1 = Bh[(t4 + 4) * PB + nc];
            uint32_t bl0 = Bl[t4 * PB + nc];
            uint32_t bl1 = Bl[(t4 + 4) * PB + nc];
            #pragma unroll
            for (int mt = 0; mt < 2; mt++) {
                mma16bf(acc[mt][nt], ah[mt], bh0, bh1);
                mma16bf(acc[mt][nt], ah[mt], bl0, bl1);
                mma16bf(acc[mt][nt], al[mt], bh0, bh1);
            }
        }

        if (hasnext) {
            __syncthreads();
            stage(cur ^ 1, k0 + 16);
        }
        __syncthreads();
    }

    #pragma unroll
    for (int mt = 0; mt < 2; mt++) {
        int r = row0 + wm + mt * 16 + g;
        #pragma unroll
        for (int nt = 0; nt < 8; nt++) {
            int c = col0 + wn + nt * 8 + 2 * t4;
            float b0v = bias[c], b1v = bias[c + 1];
            out[(size_t)r * CC + c]           = acc[mt][nt][0] + b0v;
            out[(size_t)r * CC + c + 1]       = acc[mt][nt][1] + b1v;
            out[(size_t)(r + 8) * CC + c]     = acc[mt][nt][2] + b0v;
            out[(size_t)(r + 8) * CC + c + 1] = acc[mt][nt][3] + b1v;
        }
    }
}

// ---------------------------------------------------------------------------
// sparse attention + skip; one block (128 threads) per target row
// ---------------------------------------------------------------------------
__global__ void attn1_kernel(const float* __restrict__ ln_g,
                             const float* __restrict__ ln_b) {
    int t = blockIdx.x;
    int tid = threadIdx.x, lane = tid & 31, w = tid >> 5;
    __shared__ float s_alpha[MAXDEG];
    __shared__ int   s_srcl[MAXDEG];
    __shared__ float red[128];
    int d = g_deg[t]; if (d > MAXDEG) d = MAXDEG;
    if (tid < d) s_srcl[tid] = g_src[t * MAXDEG + tid];
    __syncthreads();
    const float* qt = g_q + (size_t)t * CC;
    for (int e = w; e < d; e += 4) {
        const float* ks = g_k + (size_t)s_srcl[e] * CC;
        float p = 0.f;
        for (int c = lane; c < CC; c += 32) p += qt[c] * ks[c];
        #pragma unroll
        for (int off = 16; off; off >>= 1) p += __shfl_xor_sync(0xffffffffu, p, off);
        if (lane == 0) s_alpha[e] = p * SCALE;
    }
    __syncthreads();
    if (tid == 0) {
        float mx = -INFINITY;
        for (int e = 0; e < d; e++) mx = fmaxf(mx, s_alpha[e]);
        float sum = 0.f;
        for (int e = 0; e < d; e++) { float ex = expf(s_alpha[e] - mx); s_alpha[e] = ex; sum += ex; }
        float inv = 1.f / sum;
        for (int e = 0; e < d; e++) s_alpha[e] *= inv;
    }
    __syncthreads();
    float ov[4];
    #pragma unroll
    for (int r = 0; r < 4; r++) {
        int c = tid + 128 * r;
        float acc = g_sk[(size_t)t * CC + c];
        for (int e = 0; e < d; e++)
            acc += s_alpha[e] * g_v[(size_t)s_srcl[e] * CC + c];
        ov[r] = fmaxf(acc, 0.f);
    }
    float ls = ov[0] + ov[1] + ov[2] + ov[3];
    float ls2 = ov[0]*ov[0] + ov[1]*ov[1] + ov[2]*ov[2] + ov[3]*ov[3];
    red[tid] = ls; __syncthreads();
    for (int off = 64; off; off >>= 1) { if (tid < off) red[tid] += red[tid + off]; __syncthreads(); }
    float S = red[0]; __syncthreads();
    red[tid] = ls2; __syncthreads();
    for (int off = 64; off; off >>= 1) { if (tid < off) red[tid] += red[tid + off]; __syncthreads(); }
    float S2 = red[0]; __syncthreads();
    float mu  = S * (1.f / CC);
    float var = S2 * (1.f / CC) - mu * mu;
    float inv = rsqrtf(var + LN_EPS);
    #pragma unroll
    for (int r = 0; r < 4; r++) {
        int c = tid + 128 * r;
        g_h1[(size_t)t * CC + c] = (ov[r] - mu) * inv * ln_g[c] + ln_b[c];
    }
}

__global__ void attn2_kernel(const float* __restrict__ x3,
                             float* __restrict__ out) {
    int t = blockIdx.x;
    int tid = threadIdx.x, lane = tid & 31, w = tid >> 5;
    __shared__ float s_alpha[MAXDEG];
    __shared__ int   s_srcl[MAXDEG];
    int d = g_deg[t]; if (d > MAXDEG) d = MAXDEG;
    if (tid < d) s_srcl[tid] = g_src[t * MAXDEG + tid];
    __syncthreads();
    const float* qt = g_q + (size_t)t * CC;
    for (int e = w; e < d; e += 4) {
        const float* ks = g_k + (size_t)s_srcl[e] * CC;
        float p = 0.f;
        for (int c = lane; c < CC; c += 32) p += qt[c] * ks[c];
        #pragma unroll
        for (int off = 16; off; off >>= 1) p += __shfl_xor_sync(0xffffffffu, p, off);
        if (lane == 0) s_alpha[e] = p * SCALE;
    }
    __syncthreads();
    if (tid == 0) {
        float mx = -INFINITY;
        for (int e = 0; e < d; e++) mx = fmaxf(mx, s_alpha[e]);
        float sum = 0.f;
        for (int e = 0; e < d; e++) { float ex = expf(s_alpha[e] - mx); s_alpha[e] = ex; sum += ex; }
        float inv = 1.f / sum;
        for (int e = 0; e < d; e++) s_alpha[e] *= inv;
    }
    __syncthreads();
    #pragma unroll
    for (int r = 0; r < 4; r++) {
        int c = tid + 128 * r;
        size_t idx = (size_t)t * CC + c;
        float acc = g_sk[idx];
        for (int e = 0; e < d; e++)
            acc += s_alpha[e] * g_v[(size_t)s_srcl[e] * CC + c];
        float sig = 1.f / (1.f + expf(-acc));
        out[idx] = x3[idx] * sig;
    }
}

// ---------------------------------------------------------------------------
// launch
// ---------------------------------------------------------------------------
extern "C" void kernel_launch(void* const* d_in, const int* in_sizes, int n_in,
                              void* d_out, int out_size) {
    const float* x3  = (const float*)d_in[0];
    const float* wq1 = (const float*)d_in[1];  const float* bq1 = (const float*)d_in[2];
    const float* wk1 = (const float*)d_in[3];  const float* bk1 = (const float*)d_in[4];
    const float* wv1 = (const float*)d_in[5];  const float* bv1 = (const float*)d_in[6];
    const float* ws1 = (const float*)d_in[7];  const float* bs1 = (const float*)d_in[8];
    const float* wq2 = (const float*)d_in[9];  const float* bq2 = (const float*)d_in[10];
    const float* wk2 = (const float*)d_in[11]; const float* bk2 = (const float*)d_in[12];
    const float* wv2 = (const float*)d_in[13]; const float* bv2 = (const float*)d_in[14];
    const float* ws2 = (const float*)d_in[15]; const float* bs2 = (const float*)d_in[16];
    const float* lng = (const float*)d_in[17]; const float* lnb = (const float*)d_in[18];
    float* out = (float*)d_out;

    float *pq, *pk, *pv, *psk, *ph1;
    cudaGetSymbolAddress((void**)&pq,  g_q);
    cudaGetSymbolAddress((void**)&pk,  g_k);
    cudaGetSymbolAddress((void**)&pv,  g_v);
    cudaGetSymbolAddress((void**)&psk, g_sk);
    cudaGetSymbolAddress((void**)&ph1, g_h1);

    const int GRAM_SMEM = 4 * GA * 4;                       // 40960 B
    const int GEMM_SMEM = (4 * ASZ + 4 * BSZ) * 4;          // 41984 B
    cudaFuncSetAttribute(gram_topk_kernel,
                         cudaFuncAttributeMaxDynamicSharedMemorySize, GRAM_SMEM);
    cudaFuncSetAttribute(gemm_qkvs_kernel,
                         cudaFuncAttributeMaxDynamicSharedMemorySize, GEMM_SMEM);

    // --- graph construction ---
    zero_deg_kernel<<<(BN + 255) / 256, 256>>>();
    ssq_kernel<<<BN / 8, 256>>>(x3);
    spatial_topk_kernel<<<(NN + 255) / 256, 256>>>();
    gram_topk_kernel<<<dim3(NTILE, 1, BATCH), 256, GRAM_SMEM>>>(x3);
    adj_kernel<<<(BN + 255) / 256, 256>>>();

    dim3 ggrid(16, BN / 128);

    // --- conv1 ---
    GemmArgs a1;
    a1.A = x3;
    a1.W[0] = wq1; a1.W[1] = wk1; a1.W[2] = wv1; a1.W[3] = ws1;
    a1.bias[0] = bq1; a1.bias[1] = bk1; a1.bias[2] = bv1; a1.bias[3] = bs1;
    a1.out[0] = pq; a1.out[1] = pk; a1.out[2] = pv; a1.out[3] = psk;
    gemm_qkvs_kernel<<<ggrid, 256, GEMM_SMEM>>>(a1);
    attn1_kernel<<<BN, 128>>>(lng, lnb);

    // --- conv2 ---
    GemmArgs a2;
    a2.A = ph1;
    a2.W[0] = wq2; a2.W[1] = wk2; a2.W[2] = wv2; a2.W[3] = ws2;
    a2.bias[0] = bq2; a2.bias[1] = bk2; a2.bias[2] = bv2; a2.bias[3] = bs2;
    a2.out[0] = pq; a2.out[1] = pk; a2.out[2] = pv; a2.out[3] = psk;
    gemm_qkvs_kernel<<<ggrid, 256, GEMM_SMEM>>>(a2);
    attn2_kernel<<<BN, 128>>>(x3, out);
}

// round 16
// speedup vs baseline: 1.6576x; 1.1278x over previous
// VGG16_FPN — R16: symmetric 3xtf32 gram (R14) + bf16x3 GEMMs fed by
// GMEM-pre-packed hi/lo operands via cp.async (zero pack ALU in mainloop).
#include <cuda_runtime.h>
#include <math.h>
#include <stdint.h>

#define BATCH   8
#define CC      512
#define CH      256             // u32 pairs per row (CC/2)
#define HW      48
#define NN      2304
#define BN      (BATCH * NN)
#define MAXDEG  12
#define SCALE   0.044194173824159216f
#define LN_EPS  1e-5f
#define NPART   18
#define NTILE   171

__device__ float    g_ssq [BN];
__device__ int      g_sidx[NN * 3];
__device__ int      g_deg [BN];
__device__ int      g_src [BN * MAXDEG];
__device__ float    g_pd  [(size_t)BN * NPART * 3];
__device__ int      g_pj  [(size_t)BN * NPART * 3];
__device__ float    g_q   [(size_t)BN * CC];
__device__ float    g_k   [(size_t)BN * CC];
__device__ float    g_v   [(size_t)BN * CC];
__device__ float    g_sk  [(size_t)BN * CC];
// packed bf16 hi/lo pairs (pairs along k)
__device__ uint32_t g_xh  [(size_t)BN * CH];
__device__ uint32_t g_xl  [(size_t)BN * CH];
__device__ uint32_t g_h1h [(size_t)BN * CH];
__device__ uint32_t g_h1l [(size_t)BN * CH];
__device__ uint32_t g_wh  [(size_t)8 * CH * CC];
__device__ uint32_t g_wl  [(size_t)8 * CH * CC];

// ---------------- tf32 helpers (gram) ----------------
__device__ __forceinline__ uint32_t f2tf32(float x) {
    uint32_t r;
    asm("cvt.rna.tf32.f32 %0, %1;" : "=r"(r) : "f"(x));
    return r;
}

__device__ __forceinline__ void split_tf32(float v, uint32_t& hi, uint32_t& lo) {
    hi = f2tf32(v);
    lo = f2tf32(v - __uint_as_float(hi));
}

__device__ __forceinline__ void cp_async16(const void* smem_dst, const void* gptr) {
    uint32_t sa = (uint32_t)__cvta_generic_to_shared(smem_dst);
    asm volatile("cp.async.ca.shared.global [%0], [%1], 16;" :: "r"(sa), "l"(gptr));
}

#define CP_COMMIT() asm volatile("cp.async.commit_group;")
#define CP_WAIT(n)  asm volatile("cp.async.wait_group %0;" :: "n"(n))

__device__ __forceinline__ void mma8(float* c, const uint32_t* a,
                                     uint32_t b0, uint32_t b1) {
    asm volatile(
        "mma.sync.aligned.m16n8k8.row.col.f32.tf32.tf32.f32 "
        "{%0,%1,%2,%3},{%4,%5,%6,%7},{%8,%9},{%0,%1,%2,%3};"
        : "+f"(c[0]), "+f"(c[1]), "+f"(c[2]), "+f"(c[3])
        : "r"(a[0]), "r"(a[1]), "r"(a[2]), "r"(a[3]), "r"(b0), "r"(b1));
}

__device__ __forceinline__ void mma3(float* c,
                                     const uint32_t* ah, const uint32_t* al,
                                     uint32_t bh0, uint32_t bh1,
                                     uint32_t bl0, uint32_t bl1) {
    mma8(c, ah, bh0, bh1);
    mma8(c, ah, bl0, bl1);
    mma8(c, al, bh0, bh1);
}

// ---------------- bf16 helpers ----------------
__device__ __forceinline__ void pack_bf(float v0, float v1,
                                        uint32_t& h, uint32_t& l) {
    uint32_t hh;
    asm("cvt.rn.bf16x2.f32 %0, %1, %2;" : "=r"(hh) : "f"(v1), "f"(v0));
    h = hh;
    float f0 = __uint_as_float(hh << 16);
    float f1 = __uint_as_float(hh & 0xffff0000u);
    asm("cvt.rn.bf16x2.f32 %0, %1, %2;" : "=r"(l) : "f"(v1 - f1), "f"(v0 - f0));
}

__device__ __forceinline__ void mma16bf(float* c, const uint32_t* a,
                                        uint32_t b0, uint32_t b1) {
    asm volatile(
        "mma.sync.aligned.m16n8k16.row.col.f32.bf16.bf16.f32 "
        "{%0,%1,%2,%3},{%4,%5,%6,%7},{%8,%9},{%0,%1,%2,%3};"
        : "+f"(c[0]), "+f"(c[1]), "+f"(c[2]), "+f"(c[3])
        : "r"(a[0]), "r"(a[1]), "r"(a[2]), "r"(a[3]), "r"(b0), "r"(b1));
}

// ---------------- top3 ----------------
__device__ __forceinline__ void top3_insert(float d, int j,
                                            float& d0, int& j0,
                                            float& d1, int& j1,
                                            float& d2, int& j2) {
    bool b2 = (d < d2) || (d == d2 && j < j2);
    if (!b2) return;
    bool b1 = (d < d1) || (d == d1 && j < j1);
    if (b1) {
        d2 = d1; j2 = j1;
        bool b0 = (d < d0) || (d == d0 && j < j0);
        if (b0) { d1 = d0; j1 = j0; d0 = d; j0 = j; }
        else    { d1 = d;  j1 = j; }
    } else {
        d2 = d; j2 = j;
    }
}

__global__ void zero_deg_kernel() {
    int i = blockIdx.x * blockDim.x + threadIdx.x;
    if (i < BN) g_deg[i] = 0;
}

__global__ void ssq_kernel(const float* __restrict__ x) {
    int warp = (blockIdx.x * blockDim.x + threadIdx.x) >> 5;
    int lane = threadIdx.x & 31;
    if (warp >= BN) return;
    const float* row = x + (size_t)warp * CC;
    float s = 0.f;
    for (int c = lane; c < CC; c += 32) { float v = row[c]; s += v * v; }
    #pragma unroll
    for (int off = 16; off; off >>= 1) s += __shfl_xor_sync(0xffffffffu, s, off);
    if (lane == 0) g_ssq[warp] = s;
}

__global__ void spatial_topk_kernel() {
    int i = blockIdx.x * blockDim.x + threadIdx.x;
    if (i >= NN) return;
    int yi = i / HW, xi = i % HW;
    float d0 = INFINITY, d1 = INFINITY, d2 = INFINITY;
    int   j0 = 0x7fffffff, j1 = 0x7fffffff, j2 = 0x7fffffff;
    for (int j = 0; j < NN; j++) {
        int yj = j / HW, xj = j % HW;
        int dy = yi - yj, dx = xi - xj;
        float d = sqrtf((float)(dy * dy + dx * dx));
        top3_insert(d, j, d0, j0, d1, j1, d2, j2);
    }
    g_sidx[i * 3 + 0] = j0;
    g_sidx[i * 3 + 1] = j1;
    g_sidx[i * 3 + 2] = j2;
}

// pack x3 pairs (along k) into hi/lo
__global__ void pack_x3_kernel(const float* __restrict__ x) {
    size_t i = (size_t)blockIdx.x * blockDim.x + threadIdx.x;
    if (i >= (size_t)BN * CH) return;
    uint32_t h, l;
    pack_bf(x[2 * i], x[2 * i + 1], h, l);
    g_xh[i] = h; g_xl[i] = l;
}

// pack weights: layout [kp][n], pair = (W[2kp][n], W[2kp+1][n])
struct WArgs { const float* w[8]; };
__global__ void pack_w_kernel(WArgs a) {
    int idx = blockIdx.x * blockDim.x + threadIdx.x;   // kp*CC + n
    int m = blockIdx.y;
    int kp = idx >> 9, n = idx & 511;
    const float* w = a.w[m];
    uint32_t h, l;
    pack_bf(w[(2 * kp) * CC + n], w[(2 * kp + 1) * CC + n], h, l);
    size_t o = (size_t)m * CH * CC + idx;
    g_wh[o] = h; g_wl[o] = l;
}

// ---------------------------------------------------------------------------
// Symmetric fused Gram + topk (identical to R14).
// ---------------------------------------------------------------------------
#define GA 2560

__global__ void __launch_bounds__(256, 2) gram_topk_kernel(const float* __restrict__ X) {
    extern __shared__ float sm[];
    float* AsB[2] = { sm + 0 * GA, sm + 1 * GA };
    float* BsB[2] = { sm + 2 * GA, sm + 3 * GA };

    __shared__ float s_cd[128][2][3];
    __shared__ int   s_cj[128][2][3];
    __shared__ float s_ccd[128][4][3];
    __shared__ int   s_ccj[128][4][3];
    __shared__ float s_sq[128];
    __shared__ float s_si[128];

    int p = blockIdx.x;
    int bi = (int)((sqrtf(8.f * p + 1.f) - 1.f) * 0.5f);
    while ((bi + 1) * (bi + 2) / 2 <= p) bi++;
    while (bi * (bi + 1) / 2 > p) bi--;
    int bj = p - bi * (bi + 1) / 2;
    bool diag = (bi == bj);

    int b = blockIdx.z;
    const float* Xb = X + (size_t)b * NN * CC;
    int bNN = b * NN;
    int row0 = bi * 128, col0 = bj * 128;

    int tid = threadIdx.x;
    int warp = tid >> 5, lane = tid & 31;
    int wm = (warp >> 1) * 32;
    int wn = (warp & 1) * 64;
    int g = lane >> 2, t4 = lane & 3;
    int warpN = (warp & 1);
    int warpR = (warp >> 1);

    if (tid < 128) {
        s_si[tid] = g_ssq[bNN + row0 + tid];
        s_sq[tid] = g_ssq[bNN + col0 + tid];
    }

    int m_ld  = tid >> 2;
    int k4_ld = (tid & 3) << 2;

    #pragma unroll
    for (int i = 0; i < 2; i++) {
        int m = m_ld + 64 * i;
        int o = m * 20 + k4_ld;
        cp_async16(AsB[0] + o, Xb + (size_t)(row0 + m) * CC + k4_ld);
        cp_async16(BsB[0] + o, Xb + (size_t)(col0 + m) * CC + k4_ld);
    }
    CP_COMMIT();

    float acc[2][8][4] = {};
    for (int k0 = 0; k0 < CC; k0 += 16) {
        int cur = (k0 >> 4) & 1;
        int nxt = cur ^ 1;
        bool hasnext = (k0 + 16 < CC);
        if (hasnext) {
            #pragma unroll
            for (int i = 0; i < 2; i++) {
                int m = m_ld + 64 * i;
                int o = m * 20 + k4_ld;
                cp_async16(AsB[nxt] + o, Xb + (size_t)(row0 + m) * CC + k0 + 16 + k4_ld);
                cp_async16(BsB[nxt] + o, Xb + (size_t)(col0 + m) * CC + k0 + 16 + k4_ld);
            }
            CP_COMMIT();
            CP_WAIT(1);
        } else {
            CP_WAIT(0);
        }
        __syncthreads();

        const float* As = AsB[cur];
        const float* Bs = BsB[cur];
        #pragma unroll
        for (int kk = 0; kk < 16; kk += 8) {
            uint32_t ah[2][4], al[2][4];
            #pragma unroll
            for (int mt = 0; mt < 2; mt++) {
                int r0i = (wm + mt * 16 + g) * 20 + kk + t4;
                int r1i = r0i + 8 * 20;
                split_tf32(As[r0i],     ah[mt][0], al[mt][0]);
                split_tf32(As[r1i],     ah[mt][1], al[mt][1]);
                split_tf32(As[r0i + 4], ah[mt][2], al[mt][2]);
                split_tf32(As[r1i + 4], ah[mt][3], al[mt][3]);
            }
            #pragma unroll
            for (int nt = 0; nt < 8; nt++) {
                int nb = (wn + nt * 8 + g) * 20 + kk + t4;
                uint32_t bh0, bl0, bh1, bl1;
                split_tf32(Bs[nb],     bh0, bl0);
                split_tf32(Bs[nb + 4], bh1, bl1);
                #pragma unroll
                for (int mt = 0; mt < 2; mt++)
                    mma3(acc[mt][nt], ah[mt], al[mt], bh0, bh1, bl0, bl1);
            }
        }
        __syncthreads();
    }

    // row-pass
    #pragma unroll
    for (int mt = 0; mt < 2; mt++) {
        #pragma unroll
        for (int half = 0; half < 2; half++) {
            int r = wm + mt * 16 + g + half * 8;
            float si = s_si[r];
            float d0 = INFINITY, d1 = INFINITY, d2 = INFINITY;
            int   j0 = 0x7fffffff, j1 = 0x7fffffff, j2 = 0x7fffffff;
            #pragma unroll
            for (int nt = 0; nt < 8; nt++) {
                int cl = wn + nt * 8 + 2 * t4;
                float gv0 = acc[mt][nt][half * 2 + 0];
                float gv1 = acc[mt][nt][half * 2 + 1];
                float dd0 = sqrtf(fmaxf(si + s_sq[cl]     - 2.f * gv0, 0.f));
                float dd1 = sqrtf(fmaxf(si + s_sq[cl + 1] - 2.f * gv1, 0.f));
                top3_insert(dd0, col0 + cl,     d0, j0, d1, j1, d2, j2);
                top3_insert(dd1, col0 + cl + 1, d0, j0, d1, j1, d2, j2);
            }
            #pragma unroll
            for (int mk = 1; mk <= 2; mk <<= 1) {
                float e0 = __shfl_xor_sync(0xffffffffu, d0, mk);
                int   m0 = __shfl_xor_sync(0xffffffffu, j0, mk);
                float e1 = __shfl_xor_sync(0xffffffffu, d1, mk);
                int   m1 = __shfl_xor_sync(0xffffffffu, j1, mk);
                float e2 = __shfl_xor_sync(0xffffffffu, d2, mk);
                int   m2 = __shfl_xor_sync(0xffffffffu, j2, mk);
                top3_insert(e0, m0, d0, j0, d1, j1, d2, j2);
                top3_insert(e1, m1, d0, j0, d1, j1, d2, j2);
                top3_insert(e2, m2, d0, j0, d1, j1, d2, j2);
            }
            if (t4 == 0) {
                s_cd[r][warpN][0] = d0; s_cj[r][warpN][0] = j0;
                s_cd[r][warpN][1] = d1; s_cj[r][warpN][1] = j1;
                s_cd[r][warpN][2] = d2; s_cj[r][warpN][2] = j2;
            }
        }
    }
    __syncthreads();
    if (tid < 128) {
        float d0 = INFINITY, d1 = INFINITY, d2 = INFINITY;
        int   j0 = 0x7fffffff, j1 = 0x7fffffff, j2 = 0x7fffffff;
        #pragma unroll
        for (int w2 = 0; w2 < 2; w2++)
            #pragma unroll
            for (int e = 0; e < 3; e++)
                top3_insert(s_cd[tid][w2][e], s_cj[tid][w2][e], d0, j0, d1, j1, d2, j2);
        size_t base = ((size_t)(bNN + row0 + tid) * NPART + bj) * 3;
        g_pd[base + 0] = d0; g_pj[base + 0] = j0;
        g_pd[base + 1] = d1; g_pj[base + 1] = j1;
        g_pd[base + 2] = d2; g_pj[base + 2] = j2;
    }

    // col-pass (off-diagonal)
    if (!diag) {
        #pragma unroll
        for (int nt = 0; nt < 8; nt++) {
            #pragma unroll
            for (int cbit = 0; cbit < 2; cbit++) {
                int cl = wn + nt * 8 + 2 * t4 + cbit;
                float sj = s_sq[cl];
                float d0 = INFINITY, d1 = INFINITY, d2 = INFINITY;
                int   j0 = 0x7fffffff, j1 = 0x7fffffff, j2 = 0x7fffffff;
                #pragma unroll
                for (int mt = 0; mt < 2; mt++)
                    #pragma unroll
                    for (int half = 0; half < 2; half++) {
                        int r = wm + mt * 16 + g + half * 8;
                        float gv = acc[mt][nt][half * 2 + cbit];
                        float dd = sqrtf(fmaxf(s_si[r] + sj - 2.f * gv, 0.f));
                        top3_insert(dd, row0 + r, d0, j0, d1, j1, d2, j2);
                    }
                #pragma unroll
                for (int mk = 4; mk <= 16; mk <<= 1) {
                    float e0 = __shfl_xor_sync(0xffffffffu, d0, mk);
                    int   m0 = __shfl_xor_sync(0xffffffffu, j0, mk);
                    float e1 = __shfl_xor_sync(0xffffffffu, d1, mk);
                    int   m1 = __shfl_xor_sync(0xffffffffu, j1, mk);
                    float e2 = __shfl_xor_sync(0xffffffffu, d2, mk);
                    int   m2 = __shfl_xor_sync(0xffffffffu, j2, mk);
                    top3_insert(e0, m0, d0, j0, d1, j1, d2, j2);
                    top3_insert(e1, m1, d0, j0, d1, j1, d2, j2);
                    top3_insert(e2, m2, d0, j0, d1, j1, d2, j2);
                }
                if (g == 0) {
                    s_ccd[cl][warpR][0] = d0; s_ccj[cl][warpR][0] = j0;
                    s_ccd[cl][warpR][1] = d1; s_ccj[cl][warpR][1] = j1;
                    s_ccd[cl][warpR][2] = d2; s_ccj[cl][warpR][2] = j2;
                }
            }
        }
        __syncthreads();
        if (tid < 128) {
            float d0 = INFINITY, d1 = INFINITY, d2 = INFINITY;
            int   j0 = 0x7fffffff, j1 = 0x7fffffff, j2 = 0x7fffffff;
            #pragma unroll
            for (int w4 = 0; w4 < 4; w4++)
                #pragma unroll
                for (int e = 0; e < 3; e++)
                    top3_insert(s_ccd[tid][w4][e], s_ccj[tid][w4][e], d0, j0, d1, j1, d2, j2);
            size_t base = ((size_t)(bNN + col0 + tid) * NPART + bi) * 3;
            g_pd[base + 0] = d0; g_pj[base + 0] = j0;
            g_pd[base + 1] = d1; g_pj[base + 1] = j1;
            g_pd[base + 2] = d2; g_pj[base + 2] = j2;
        }
    }
}

__global__ void adj_kernel() {
    int row = blockIdx.x * blockDim.x + threadIdx.x;
    if (row >= BN) return;
    int i = row % NN;
    float d0 = INFINITY, d1 = INFINITY, d2 = INFINITY;
    int   j0 = 0x7fffffff, j1 = 0x7fffffff, j2 = 0x7fffffff;
    size_t base = (size_t)row * NPART * 3;
    for (int s = 0; s < NPART * 3; s++)
        top3_insert(g_pd[base + s], g_pj[base + s], d0, j0, d1, j1, d2, j2);
    int f[3] = { j0, j1, j2 };
    int s0 = g_sidx[i * 3 + 0], s1 = g_sidx[i * 3 + 1], s2 = g_sidx[i * 3 + 2];
    int b = row / NN;
    #pragma unroll
    for (int e = 0; e < 3; e++) {
        if (f[e] == s0 || f[e] == s1 || f[e] == s2) {
            int tgt = b * NN + f[e];
            int pos = atomicAdd(&g_deg[tgt], 1);
            if (pos < MAXDEG) g_src[tgt * MAXDEG + pos] = row;
        }
    }
}

// ---------------------------------------------------------------------------
// Merged QKVS GEMM — bf16x3, operands pre-packed in GMEM, staged via cp.async.
// SMEM: A [128][PA=12] u32 (8 pairs + pad), B [8][PB=136] u32.
// dynamic smem: 2 * (2*ASZ + 2*BSZ) * 4 = 41984 B
// ---------------------------------------------------------------------------
#define PA 12
#define PB 136
#define ASZ (128 * PA)
#define BSZ (8 * PB)

struct GemmArgs {
    const uint32_t* Ah;   // packed activations hi [rows][CH]
    const uint32_t* Al;
    const float* bias[4];
    float* out[4];
};

__global__ void __launch_bounds__(256, 2) gemm_qkvs_kernel(GemmArgs args, int wbase) {
    extern __shared__ uint32_t smu[];
    uint32_t* AhB[2] = { smu + 0 * ASZ, smu + 1 * ASZ };
    uint32_t* AlB[2] = { smu + 2 * ASZ, smu + 3 * ASZ };
    uint32_t* BhB[2] = { smu + 4 * ASZ + 0 * BSZ, smu + 4 * ASZ + 1 * BSZ };
    uint32_t* BlB[2] = { smu + 4 * ASZ + 2 * BSZ, smu + 4 * ASZ + 3 * BSZ };

    int wsel = blockIdx.x >> 2;
    int col0 = (blockIdx.x & 3) << 7;
    int row0 = blockIdx.y * 128;
    const uint32_t* Ahg = args.Ah;
    const uint32_t* Alg = args.Al;
    const uint32_t* Whg = g_wh + (size_t)(wbase + wsel) * CH * CC;
    const uint32_t* Wlg = g_wl + (size_t)(wbase + wsel) * CH * CC;
    const float* bias = args.bias[wsel];
    float* out = args.out[wsel];

    int tid = threadIdx.x;
    int warp = tid >> 5, lane = tid & 31;
    int wm = (warp >> 1) * 32;
    int wn = (warp & 1) * 64;
    int g = lane >> 2, t4 = lane & 3;

    int a_row = tid >> 1;              // 0..127
    int a_ch  = (tid & 1) * 4;         // pair-chunk 0 or 4
    int b_row = tid >> 5;              // 0..7 k-pair rows
    int b_ch  = (lane) * 4;            // 0..124

    auto stage = [&](int buf, int k0) {
        int kp0 = k0 >> 1;             // pair origin
        const uint32_t* sa_h = Ahg + (size_t)(row0 + a_row) * CH + kp0 + a_ch;
        const uint32_t* sa_l = Alg + (size_t)(row0 + a_row) * CH + kp0 + a_ch;
        cp_async16(AhB[buf] + a_row * PA + a_ch, sa_h);
        cp_async16(AlB[buf] + a_row * PA + a_ch, sa_l);
        const uint32_t* sb_h = Whg + (size_t)(kp0 + b_row) * CC + col0 + b_ch;
        const uint32_t* sb_l = Wlg + (size_t)(kp0 + b_row) * CC + col0 + b_ch;
        cp_async16(BhB[buf] + b_row * PB + b_ch, sb_h);
        cp_async16(BlB[buf] + b_row * PB + b_ch, sb_l);
    };

    stage(0, 0);
    CP_COMMIT();

    float acc[2][8][4] = {};
    for (int k0 = 0; k0 < CC; k0 += 16) {
        int cur = (k0 >> 4) & 1;
        int nxt = cur ^ 1;
        bool hasnext = (k0 + 16 < CC);
        if (hasnext) {
            stage(nxt, k0 + 16);
            CP_COMMIT();
            CP_WAIT(1);
        } else {
            CP_WAIT(0);
        }
        __syncthreads();

        const uint32_t* Ah = AhB[cur]; const uint32_t* Al = AlB[cur];
        const uint32_t* Bh = BhB[cur]; const uint32_t* Bl = BlB[cur];

        uint32_t ah[2][4], al[2][4];
        #pragma unroll
        for (int mt = 0; mt < 2; mt++) {
            int r0 = (wm + mt * 16 + g) * PA;
            int r1 = r0 + 8 * PA;
            ah[mt][0] = Ah[r0 + t4];     al[mt][0] = Al[r0 + t4];
            ah[mt][1] = Ah[r1 + t4];     al[mt][1] = Al[r1 + t4];
            ah[mt][2] = Ah[r0 + t4 + 4]; al[mt][2] = Al[r0 + t4 + 4];
            ah[mt][3] = Ah[r1 + t4 + 4]; al[mt][3] = Al[r1 + t4 + 4];
        }
        #pragma unroll
        for (int nt = 0; nt < 8; nt++) {
            int nc = wn + nt * 8 + g;
            uint32_t bh0 = Bh[t4 * PB + nc];
            uint32_t bh1 = Bh[(t4 + 4) * PB + nc];
            uint32_t bl0 = Bl[t4 * PB + nc];
            uint32_t bl1 = Bl[(t4 + 4) * PB + nc];
            #pragma unroll
            for (int mt = 0; mt < 2; mt++) {
                mma16bf(acc[mt][nt], ah[mt], bh0, bh1);
                mma16bf(acc[mt][nt], ah[mt], bl0, bl1);
                mma16bf(acc[mt][nt], al[mt], bh0, bh1);
            }
        }
        __syncthreads();
    }

    #pragma unroll
    for (int mt = 0; mt < 2; mt++) {
        int r = row0 + wm + mt * 16 + g;
        #pragma unroll
        for (int nt = 0; nt < 8; nt++) {
            int c = col0 + wn + nt * 8 + 2 * t4;
            float b0v = bias[c], b1v = bias[c + 1];
            out[(size_t)r * CC + c]           = acc[mt][nt][0] + b0v;
            out[(size_t)r * CC + c + 1]       = acc[mt][nt][1] + b1v;
            out[(size_t)(r + 8) * CC + c]     = acc[mt][nt][2] + b0v;
            out[(size_t)(r + 8) * CC + c + 1] = acc[mt][nt][3] + b1v;
        }
    }
}

// ---------------------------------------------------------------------------
// attn1: sparse attention + ReLU + LN; writes h1 PACKED (hi/lo) for conv2.
// float4 column mapping: thread owns columns 4tid..4tid+3.
// ---------------------------------------------------------------------------
__global__ void attn1_kernel(const float* __restrict__ ln_g,
                             const float* __restrict__ ln_b) {
    int t = blockIdx.x;
    int tid = threadIdx.x, lane = tid & 31, w = tid >> 5;
    __shared__ float s_alpha[MAXDEG];
    __shared__ int   s_srcl[MAXDEG];
    __shared__ float red[128];
    int d = g_deg[t]; if (d > MAXDEG) d = MAXDEG;
    if (tid < d) s_srcl[tid] = g_src[t * MAXDEG + tid];
    __syncthreads();
    const float* qt = g_q + (size_t)t * CC;
    for (int e = w; e < d; e += 4) {
        const float* ks = g_k + (size_t)s_srcl[e] * CC;
        float p = 0.f;
        for (int c = lane; c < CC; c += 32) p += qt[c] * ks[c];
        #pragma unroll
        for (int off = 16; off; off >>= 1) p += __shfl_xor_sync(0xffffffffu, p, off);
        if (lane == 0) s_alpha[e] = p * SCALE;
    }
    __syncthreads();
    if (tid == 0) {
        float mx = -INFINITY;
        for (int e = 0; e < d; e++) mx = fmaxf(mx, s_alpha[e]);
        float sum = 0.f;
        for (int e = 0; e < d; e++) { float ex = expf(s_alpha[e] - mx); s_alpha[e] = ex; sum += ex; }
        float inv = 1.f / sum;
        for (int e = 0; e < d; e++) s_alpha[e] *= inv;
    }
    __syncthreads();
    int c4 = tid * 4;
    float4 a4 = *(const float4*)(g_sk + (size_t)t * CC + c4);
    for (int e = 0; e < d; e++) {
        float al = s_alpha[e];
        float4 v4 = *(const float4*)(g_v + (size_t)s_srcl[e] * CC + c4);
        a4.x += al * v4.x; a4.y += al * v4.y; a4.z += al * v4.z; a4.w += al * v4.w;
    }
    float ov[4] = { fmaxf(a4.x, 0.f), fmaxf(a4.y, 0.f),
                    fmaxf(a4.z, 0.f), fmaxf(a4.w, 0.f) };
    float ls = ov[0] + ov[1] + ov[2] + ov[3];
    float ls2 = ov[0]*ov[0] + ov[1]*ov[1] + ov[2]*ov[2] + ov[3]*ov[3];
    red[tid] = ls; __syncthreads();
    for (int off = 64; off; off >>= 1) { if (tid < off) red[tid] += red[tid + off]; __syncthreads(); }
    float S = red[0]; __syncthreads();
    red[tid] = ls2; __syncthreads();
    for (int off = 64; off; off >>= 1) { if (tid < off) red[tid] += red[tid + off]; __syncthreads(); }
    float S2 = red[0]; __syncthreads();
    float mu  = S * (1.f / CC);
    float var = S2 * (1.f / CC) - mu * mu;
    float inv = rsqrtf(var + LN_EPS);
    float4 gg = *(const float4*)(ln_g + c4);
    float4 bb = *(const float4*)(ln_b + c4);
    float v0 = (ov[0] - mu) * inv * gg.x + bb.x;
    float v1 = (ov[1] - mu) * inv * gg.y + bb.y;
    float v2 = (ov[2] - mu) * inv * gg.z + bb.z;
    float v3 = (ov[3] - mu) * inv * gg.w + bb.w;
    uint32_t h0, l0, h1, l1;
    pack_bf(v0, v1, h0, l0);
    pack_bf(v2, v3, h1, l1);
    size_t ob = (size_t)t * CH + 2 * tid;
    g_h1h[ob] = h0; g_h1h[ob + 1] = h1;
    g_h1l[ob] = l0; g_h1l[ob + 1] = l1;
}

__global__ void attn2_kernel(const float* __restrict__ x3,
                             float* __restrict__ out) {
    int t = blockIdx.x;
    int tid = threadIdx.x, lane = tid & 31, w = tid >> 5;
    __shared__ float s_alpha[MAXDEG];
    __shared__ int   s_srcl[MAXDEG];
    int d = g_deg[t]; if (d > MAXDEG) d = MAXDEG;
    if (tid < d) s_srcl[tid] = g_src[t * MAXDEG + tid];
    __syncthreads();
    const float* qt = g_q + (size_t)t * CC;
    for (int e = w; e < d; e += 4) {
        const float* ks = g_k + (size_t)s_srcl[e] * CC;
        float p = 0.f;
        for (int c = lane; c < CC; c += 32) p += qt[c] * ks[c];
        #pragma unroll
        for (int off = 16; off; off >>= 1) p += __shfl_xor_sync(0xffffffffu, p, off);
        if (lane == 0) s_alpha[e] = p * SCALE;
    }
    __syncthreads();
    if (tid == 0) {
        float mx = -INFINITY;
        for (int e = 0; e < d; e++) mx = fmaxf(mx, s_alpha[e]);
        float sum = 0.f;
        for (int e = 0; e < d; e++) { float ex = expf(s_alpha[e] - mx); s_alpha[e] = ex; sum += ex; }
        float inv = 1.f / sum;
        for (int e = 0; e < d; e++) s_alpha[e] *= inv;
    }
    __syncthreads();
    int c4 = tid * 4;
    size_t idx = (size_t)t * CC + c4;
    float4 a4 = *(const float4*)(g_sk + idx);
    for (int e = 0; e < d; e++) {
        float al = s_alpha[e];
        float4 v4 = *(const float4*)(g_v + (size_t)s_srcl[e] * CC + c4);
        a4.x += al * v4.x; a4.y += al * v4.y; a4.z += al * v4.z; a4.w += al * v4.w;
    }
    float4 x4 = *(const float4*)(x3 + idx);
    float4 o4;
    o4.x = x4.x / (1.f + expf(-a4.x));
    o4.y = x4.y / (1.f + expf(-a4.y));
    o4.z = x4.z / (1.f + expf(-a4.z));
    o4.w = x4.w / (1.f + expf(-a4.w));
    *(float4*)(out + idx) = o4;
}

// ---------------------------------------------------------------------------
// launch
// ---------------------------------------------------------------------------
extern "C" void kernel_launch(void* const* d_in, const int* in_sizes, int n_in,
                              void* d_out, int out_size) {
    const float* x3  = (const float*)d_in[0];
    const float* wq1 = (const float*)d_in[1];  const float* bq1 = (const float*)d_in[2];
    const float* wk1 = (const float*)d_in[3];  const float* bk1 = (const float*)d_in[4];
    const float* wv1 = (const float*)d_in[5];  const float* bv1 = (const float*)d_in[6];
    const float* ws1 = (const float*)d_in[7];  const float* bs1 = (const float*)d_in[8];
    const float* wq2 = (const float*)d_in[9];  const float* bq2 = (const float*)d_in[10];
    const float* wk2 = (const float*)d_in[11]; const float* bk2 = (const float*)d_in[12];
    const float* wv2 = (const float*)d_in[13]; const float* bv2 = (const float*)d_in[14];
    const float* ws2 = (const float*)d_in[15]; const float* bs2 = (const float*)d_in[16];
    const float* lng = (const float*)d_in[17]; const float* lnb = (const float*)d_in[18];
    float* out = (float*)d_out;

    float *pq, *pk, *pv, *psk;
    uint32_t *pxh, *pxl, *ph1h, *ph1l;
    cudaGetSymbolAddress((void**)&pq,   g_q);
    cudaGetSymbolAddress((void**)&pk,   g_k);
    cudaGetSymbolAddress((void**)&pv,   g_v);
    cudaGetSymbolAddress((void**)&psk,  g_sk);
    cudaGetSymbolAddress((void**)&pxh,  g_xh);
    cudaGetSymbolAddress((void**)&pxl,  g_xl);
    cudaGetSymbolAddress((void**)&ph1h, g_h1h);
    cudaGetSymbolAddress((void**)&ph1l, g_h1l);

    const int GRAM_SMEM = 4 * GA * 4;
    const int GEMM_SMEM = (4 * ASZ + 4 * BSZ) * 4;
    cudaFuncSetAttribute(gram_topk_kernel,
                         cudaFuncAttributeMaxDynamicSharedMemorySize, GRAM_SMEM);
    cudaFuncSetAttribute(gemm_qkvs_kernel,
                         cudaFuncAttributeMaxDynamicSharedMemorySize, GEMM_SMEM);

    // --- prep + graph construction ---
    zero_deg_kernel<<<(BN + 255) / 256, 256>>>();
    ssq_kernel<<<BN / 8, 256>>>(x3);
    spatial_topk_kernel<<<(NN + 255) / 256, 256>>>();
    pack_x3_kernel<<<(int)(((size_t)BN * CH + 255) / 256), 256>>>(x3);
    WArgs wa;
    wa.w[0] = wq1; wa.w[1] = wk1; wa.w[2] = wv1; wa.w[3] = ws1;
    wa.w[4] = wq2; wa.w[5] = wk2; wa.w[6] = wv2; wa.w[7] = ws2;
    pack_w_kernel<<<dim3(CH * CC / 256, 8), 256>>>(wa);

    gram_topk_kernel<<<dim3(NTILE, 1, BATCH), 256, GRAM_SMEM>>>(x3);
    adj_kernel<<<(BN + 255) / 256, 256>>>();

    dim3 ggrid(16, BN / 128);

    // --- conv1 ---
    GemmArgs a1;
    a1.Ah = pxh; a1.Al = pxl;
    a1.bias[0] = bq1; a1.bias[1] = bk1; a1.bias[2] = bv1; a1.bias[3] = bs1;
    a1.out[0] = pq; a1.out[1] = pk; a1.out[2] = pv; a1.out[3] = psk;
    gemm_qkvs_kernel<<<ggrid, 256, GEMM_SMEM>>>(a1, 0);
    attn1_kernel<<<BN, 128>>>(lng, lnb);

    // --- conv2 ---
    GemmArgs a2;
    a2.Ah = ph1h; a2.Al = ph1l;
    a2.bias[0] = bq2; a2.bias[1] = bk2; a2.bias[2] = bv2; a2.bias[3] = bs2;
    a2.out[0] = pq; a2.out[1] = pk; a2.out[2] = pv; a2.out[3] = psk;
    gemm_qkvs_kernel<<<ggrid, 256, GEMM_SMEM>>>(a2, 4);
    attn2_kernel<<<BN, 128>>>(x3, out);
}